// round 13
// baseline (speedup 1.0000x reference)
#include <cuda_runtime.h>
#include <cuda_bf16.h>
#include <cuda_fp16.h>
#include <cstdint>
#include <cstdio>

#define NN 100000
#define FF 256
#define EMAX 3200000

typedef unsigned long long ull;

// ================= scratch (device globals; no allocation allowed) =================
__device__ __align__(256) __half g_xwh[2 * (size_t)NN * FF];   // X@W_A, X@W_A2 fp16 (SpMM gather)
__device__ __align__(256) __half g_acch[2 * (size_t)NN * FF];  // spmm results fp16
__device__ __align__(256) __half g_mlph[(size_t)NN * FF];      // relu(X@W_mlp) fp16
__device__ float g_colsum[3 * FF];
__device__ float g_v[3 * FF];
__device__ __nv_bfloat16 g_xhi[(size_t)NN * FF];
__device__ __nv_bfloat16 g_xlo[(size_t)NN * FF];
__device__ __nv_bfloat16 g_wthi[3 * FF * FF];
__device__ __nv_bfloat16 g_wtlo[3 * FF * FF];
// counting-sort scratch
__device__ int g_cnt[2 * NN];
__device__ int g_ptr[2 * (NN + 1)];
__device__ int g_off[2 * NN];
__device__ __align__(256) ull g_edges[2 * (size_t)EMAX];  // packed (val<<32 | col), row-sorted

// ================= helpers =================
__device__ __forceinline__ uint32_t smem_u32(const void* p) {
    uint32_t a;
    asm("{ .reg .u64 t; cvta.to.shared.u64 t, %1; cvt.u32.u64 %0, t; }" : "=r"(a) : "l"(p));
    return a;
}
__device__ __forceinline__ void cp_async16(uint32_t dst, const void* src, uint32_t bytes) {
    asm volatile("cp.async.ca.shared.global [%0], [%1], 16, %2;"
                 :: "r"(dst), "l"(src), "r"(bytes) : "memory");
}
#define CP_COMMIT() asm volatile("cp.async.commit_group;" ::: "memory")
#define CP_WAIT0()  asm volatile("cp.async.wait_group 0;" ::: "memory")
#define CP_WAIT1()  asm volatile("cp.async.wait_group 1;" ::: "memory")

__device__ __forceinline__ void ldsm_x4(uint32_t& r0, uint32_t& r1, uint32_t& r2, uint32_t& r3,
                                        uint32_t addr) {
    asm volatile("ldmatrix.sync.aligned.m8n8.x4.shared.b16 {%0,%1,%2,%3}, [%4];"
                 : "=r"(r0), "=r"(r1), "=r"(r2), "=r"(r3) : "r"(addr));
}
__device__ __forceinline__ void ldsm_x2(uint32_t& r0, uint32_t& r1, uint32_t addr) {
    asm volatile("ldmatrix.sync.aligned.m8n8.x2.shared.b16 {%0,%1}, [%2];"
                 : "=r"(r0), "=r"(r1) : "r"(addr));
}
__device__ __forceinline__ void mma_bf16(float* d, const uint32_t* a, const uint32_t* b) {
    asm volatile(
        "mma.sync.aligned.m16n8k16.row.col.f32.bf16.bf16.f32 "
        "{%0,%1,%2,%3}, {%4,%5,%6,%7}, {%8,%9}, {%0,%1,%2,%3};"
        : "+f"(d[0]), "+f"(d[1]), "+f"(d[2]), "+f"(d[3])
        : "r"(a[0]), "r"(a[1]), "r"(a[2]), "r"(a[3]), "r"(b[0]), "r"(b[1]));
}
__device__ __forceinline__ void red_add_v4(float* p, float4 v) {
    asm volatile("red.relaxed.gpu.global.add.v4.f32 [%0], {%1,%2,%3,%4};"
                 :: "l"(p), "f"(v.x), "f"(v.y), "f"(v.z), "f"(v.w) : "memory");
}

// ================= zero histograms + colsum =================
__global__ void zero_small_kernel() {
    int t = blockIdx.x * blockDim.x + threadIdx.x;
    if (t < 2 * NN) g_cnt[t] = 0;
    if (t < 3 * FF) g_colsum[t] = 0.f;
}

// ================= convert X -> bf16 hi/lo =================
__global__ __launch_bounds__(256) void convert_x_kernel(const float* __restrict__ X, int n) {
    size_t total4 = (size_t)n * (FF / 4);
    size_t stride = (size_t)gridDim.x * blockDim.x;
    for (size_t i4 = (size_t)blockIdx.x * blockDim.x + threadIdx.x; i4 < total4; i4 += stride) {
        float4 x = reinterpret_cast<const float4*>(X)[i4];
        __nv_bfloat16 h0 = __float2bfloat16_rn(x.x);
        __nv_bfloat16 h1 = __float2bfloat16_rn(x.y);
        __nv_bfloat16 h2 = __float2bfloat16_rn(x.z);
        __nv_bfloat16 h3 = __float2bfloat16_rn(x.w);
        __nv_bfloat16 l0 = __float2bfloat16_rn(x.x - __bfloat162float(h0));
        __nv_bfloat16 l1 = __float2bfloat16_rn(x.y - __bfloat162float(h1));
        __nv_bfloat16 l2 = __float2bfloat16_rn(x.z - __bfloat162float(h2));
        __nv_bfloat16 l3 = __float2bfloat16_rn(x.w - __bfloat162float(h3));
        size_t i = i4 * 4;
        reinterpret_cast<__nv_bfloat162*>(g_xhi + i)[0] = __nv_bfloat162(h0, h1);
        reinterpret_cast<__nv_bfloat162*>(g_xhi + i)[1] = __nv_bfloat162(h2, h3);
        reinterpret_cast<__nv_bfloat162*>(g_xlo + i)[0] = __nv_bfloat162(l0, l1);
        reinterpret_cast<__nv_bfloat162*>(g_xlo + i)[1] = __nv_bfloat162(l2, l3);
    }
}

// ================= transpose + convert W -> bf16 hi/lo =================
__global__ __launch_bounds__(256) void convert_w_kernel(
    const float* __restrict__ W0, const float* __restrict__ W1, const float* __restrict__ W2)
{
    int z = blockIdx.y;
    const float* W = (z == 0) ? W0 : ((z == 1) ? W1 : W2);
    int t = blockIdx.x * 256 + threadIdx.x;
    int k = t & 255;
    int nn = t >> 8;
    float x = W[k * 256 + nn];
    __nv_bfloat16 h = __float2bfloat16_rn(x);
    __nv_bfloat16 l = __float2bfloat16_rn(x - __bfloat162float(h));
    g_wthi[(size_t)z * 65536 + nn * 256 + k] = h;
    g_wtlo[(size_t)z * 65536 + nn * 256 + k] = l;
}

// ================= HMMA GEMM (3xBF16 split); fp16 outputs (relu for z==2) ========
static constexpr int TSTRIDE = 40;
static constexpr int TILE_B = 128 * TSTRIDE * 2;
static constexpr int STAGE_B = 4 * TILE_B;
static constexpr uint32_t GEMM_SMEM_BYTES = 2 * STAGE_B + 256;

__global__ __launch_bounds__(256, 1) void gemm_mma_kernel(int n)
{
    extern __shared__ char dynsmem[];
    uint32_t raw = smem_u32(dynsmem);
    uint32_t base = (raw + 127) & ~127u;

    const int z = blockIdx.z;
    const __nv_bfloat16* __restrict__ WH = g_wthi + (size_t)z * 65536;
    const __nv_bfloat16* __restrict__ WL = g_wtlo + (size_t)z * 65536;
    __half* outh = (z == 2) ? g_mlph : (g_xwh + (size_t)z * NN * FF);

    const int row0 = blockIdx.x * 128;
    const int col0 = blockIdx.y * 128;
    const int tid = threadIdx.x;
    const int wid = tid >> 5;
    const int lane = tid & 31;
    const int warp_m = wid & 1;
    const int warp_n = wid >> 1;

    const uint32_t AH = 0, AL = TILE_B, BH = 2 * TILE_B, BL = 3 * TILE_B;

    auto load_chunk = [&](int s, int c) {
        const uint32_t st = base + s * STAGE_B;
        const int k0 = c * 32;
#pragma unroll
        for (int it = 0; it < 2; it++) {
            int idx = tid + it * 256;
            int r = idx >> 2;
            int q = idx & 3;
            uint32_t dsto = (uint32_t)(r * (TSTRIDE * 2) + q * 16);
            int gr = row0 + r;
            uint32_t sz = (gr < n) ? 16u : 0u;
            const __nv_bfloat16* sa = g_xhi + (size_t)(gr < n ? gr : 0) * FF + k0 + q * 8;
            const __nv_bfloat16* sl = g_xlo + (size_t)(gr < n ? gr : 0) * FF + k0 + q * 8;
            cp_async16(st + AH + dsto, sa, sz);
            cp_async16(st + AL + dsto, sl, sz);
            int nr = col0 + r;
            cp_async16(st + BH + dsto, WH + (size_t)nr * FF + k0 + q * 8, 16);
            cp_async16(st + BL + dsto, WL + (size_t)nr * FF + k0 + q * 8, 16);
        }
        CP_COMMIT();
    };

    float acc[4][4][4];
#pragma unroll
    for (int i = 0; i < 4; i++)
#pragma unroll
        for (int j = 0; j < 4; j++)
#pragma unroll
            for (int q = 0; q < 4; q++) acc[i][j][q] = 0.f;

    const uint32_t a_off = (uint32_t)((warp_m * 64 + (lane & 15)) * (TSTRIDE * 2) + (lane >> 4) * 16);
    const uint32_t b_off = (uint32_t)((warp_n * 32 + (lane & 7)) * (TSTRIDE * 2) + ((lane >> 3) & 1) * 16);

    load_chunk(0, 0);

    for (int c = 0; c < 8; c++) {
        const int s = c & 1;
        if (c < 7) load_chunk(s ^ 1, c + 1);
        if (c < 7) { CP_WAIT1(); } else { CP_WAIT0(); }
        __syncthreads();

        const uint32_t st = base + s * STAGE_B;
#pragma unroll
        for (int ks = 0; ks < 2; ks++) {
            uint32_t ah[4][4], al[4][4], bh[4][2], bl[4][2];
#pragma unroll
            for (int mt = 0; mt < 4; mt++) {
                uint32_t ao = st + a_off + (uint32_t)(mt * 16 * TSTRIDE * 2 + ks * 32);
                ldsm_x4(ah[mt][0], ah[mt][1], ah[mt][2], ah[mt][3], ao + AH);
                ldsm_x4(al[mt][0], al[mt][1], al[mt][2], al[mt][3], ao + AL);
            }
#pragma unroll
            for (int nt = 0; nt < 4; nt++) {
                uint32_t bo = st + b_off + (uint32_t)(nt * 8 * TSTRIDE * 2 + ks * 32);
                ldsm_x2(bh[nt][0], bh[nt][1], bo + BH);
                ldsm_x2(bl[nt][0], bl[nt][1], bo + BL);
            }
#pragma unroll
            for (int mt = 0; mt < 4; mt++)
#pragma unroll
                for (int nt = 0; nt < 4; nt++) {
                    mma_bf16(acc[mt][nt], ah[mt], bh[nt]);
                    mma_bf16(acc[mt][nt], ah[mt], bl[nt]);
                    mma_bf16(acc[mt][nt], al[mt], bh[nt]);
                }
        }
        __syncthreads();
    }

    const int er = lane >> 2;
    const int ec = (lane & 3) * 2;
#pragma unroll
    for (int mt = 0; mt < 4; mt++) {
#pragma unroll
        for (int nt = 0; nt < 4; nt++) {
            int col = col0 + warp_n * 32 + nt * 8 + ec;
            int r1 = row0 + warp_m * 64 + mt * 16 + er;
            int r2 = r1 + 8;
            float2 v1 = make_float2(acc[mt][nt][0], acc[mt][nt][1]);
            float2 v2 = make_float2(acc[mt][nt][2], acc[mt][nt][3]);
            if (z == 2) {
                v1.x = fmaxf(v1.x, 0.f); v1.y = fmaxf(v1.y, 0.f);
                v2.x = fmaxf(v2.x, 0.f); v2.y = fmaxf(v2.y, 0.f);
            }
            __half2 h1 = __float22half2_rn(v1);
            __half2 h2 = __float22half2_rn(v2);
            if (r1 < n) *reinterpret_cast<__half2*>(outh + (size_t)r1 * FF + col) = h1;
            if (r2 < n) *reinterpret_cast<__half2*>(outh + (size_t)r2 * FF + col) = h2;
        }
    }
}

// ================= counting sort: histogram =================
__global__ __launch_bounds__(256) void hist_kernel(
    const int* __restrict__ rowA, const int* __restrict__ rowB, int E)
{
    const int m = blockIdx.y;
    const int* __restrict__ row = (m == 0) ? rowA : rowB;
    int* cnt = g_cnt + m * NN;
    int stride = gridDim.x * blockDim.x;
    for (int i = blockIdx.x * blockDim.x + threadIdx.x; i < E; i += stride)
        atomicAdd(&cnt[row[i]], 1);
}

// ================= counting sort: exclusive scan (1 block per matrix) ============
__global__ __launch_bounds__(1024) void scan_kernel(int E) {
    const int m = blockIdx.x;
    const int* cnt = g_cnt + m * NN;
    int* ptr = g_ptr + m * (NN + 1);
    int* off = g_off + m * NN;
    __shared__ int wsum[32];
    __shared__ int carry_s;
    int tid = threadIdx.x;
    int lane = tid & 31, wid = tid >> 5;
    if (tid == 0) carry_s = 0;
    __syncthreads();
    for (int basei = 0; basei < NN; basei += 1024) {
        int i = basei + tid;
        int v = (i < NN) ? cnt[i] : 0;
        int x = v;
#pragma unroll
        for (int o = 1; o < 32; o <<= 1) {
            int y = __shfl_up_sync(0xffffffffu, x, o);
            if (lane >= o) x += y;
        }
        if (lane == 31) wsum[wid] = x;
        __syncthreads();
        if (wid == 0) {
            int s = wsum[lane];
#pragma unroll
            for (int o = 1; o < 32; o <<= 1) {
                int y = __shfl_up_sync(0xffffffffu, s, o);
                if (lane >= o) s += y;
            }
            wsum[lane] = s;
        }
        __syncthreads();
        int incl = x + (wid > 0 ? wsum[wid - 1] : 0);
        int excl = incl - v + carry_s;
        if (i < NN) { ptr[i] = excl; off[i] = excl; }
        __syncthreads();
        if (tid == 1023) carry_s += incl;
        __syncthreads();
    }
    if (threadIdx.x == 0) ptr[NN] = E;
}

// ================= counting sort: scatter packed (val,col) =================
__global__ __launch_bounds__(256) void scatter_kernel(
    const int* __restrict__ rowA, const int* __restrict__ colA, const float* __restrict__ valA,
    const int* __restrict__ rowB, const int* __restrict__ colB, const float* __restrict__ valB,
    int E)
{
    const int m = blockIdx.y;
    const int* __restrict__ row = (m == 0) ? rowA : rowB;
    const int* __restrict__ col = (m == 0) ? colA : colB;
    const float* __restrict__ val = (m == 0) ? valA : valB;
    int* off = g_off + m * NN;
    ull* edges = g_edges + (size_t)m * EMAX;
    int stride = gridDim.x * blockDim.x;
    for (int i = blockIdx.x * blockDim.x + threadIdx.x; i < E; i += stride) {
        int r = row[i];
        int pos = atomicAdd(&off[r], 1);
        ull e = ((ull)__float_as_uint(val[i]) << 32) | (uint32_t)col[i];
        edges[pos] = e;
    }
}

// ================= CSR SpMM: fp16 gather + fp16 result, one warp per row ========
__global__ __launch_bounds__(256) void spmm_csr_kernel(int n)
{
    const int m = blockIdx.y;
    const __half* __restrict__ x = g_xwh + (size_t)m * NN * FF;
    __half* __restrict__ acc = g_acch + (size_t)m * NN * FF;
    const ull* __restrict__ edges = g_edges + (size_t)m * EMAX;
    const int* __restrict__ ptr = g_ptr + m * (NN + 1);

    int warp = threadIdx.x >> 5;
    int lane = threadIdx.x & 31;
    int r = blockIdx.x * 8 + warp;
    if (r >= n) return;

    int s = ptr[r], e = ptr[r + 1];
    float a[8];
#pragma unroll
    for (int i = 0; i < 8; i++) a[i] = 0.f;

    for (int b = s; b < e; b += 32) {
        int cntb = min(32, e - b);
        ull my = (b + lane < e) ? __ldg(edges + b + lane) : 0ull;
        for (int j = 0; j < cntb; j++) {
            ull ed = __shfl_sync(0xffffffffu, my, j);
            int c = (int)(uint32_t)ed;
            float v = __uint_as_float((uint32_t)(ed >> 32));
            uint4 h = __ldg(reinterpret_cast<const uint4*>(x + (size_t)c * FF) + lane);
            float2 f0 = __half22float2(*reinterpret_cast<__half2*>(&h.x));
            float2 f1 = __half22float2(*reinterpret_cast<__half2*>(&h.y));
            float2 f2 = __half22float2(*reinterpret_cast<__half2*>(&h.z));
            float2 f3 = __half22float2(*reinterpret_cast<__half2*>(&h.w));
            a[0] = fmaf(v, f0.x, a[0]); a[1] = fmaf(v, f0.y, a[1]);
            a[2] = fmaf(v, f1.x, a[2]); a[3] = fmaf(v, f1.y, a[3]);
            a[4] = fmaf(v, f2.x, a[4]); a[5] = fmaf(v, f2.y, a[5]);
            a[6] = fmaf(v, f3.x, a[6]); a[7] = fmaf(v, f3.y, a[7]);
        }
    }
    uint4 o;
    __half2 p0 = __float22half2_rn(make_float2(a[0], a[1]));
    __half2 p1 = __float22half2_rn(make_float2(a[2], a[3]));
    __half2 p2 = __float22half2_rn(make_float2(a[4], a[5]));
    __half2 p3 = __float22half2_rn(make_float2(a[6], a[7]));
    o.x = *reinterpret_cast<uint32_t*>(&p0);
    o.y = *reinterpret_cast<uint32_t*>(&p1);
    o.z = *reinterpret_cast<uint32_t*>(&p2);
    o.w = *reinterpret_cast<uint32_t*>(&p3);
    *(reinterpret_cast<uint4*>(acc + (size_t)r * FF) + lane) = o;
}

// ================= column sums over fp16 branch outputs =================
// 256 threads = 8 row-lanes x 32 col-octets; each thread sums 8 cols, fp32.
__global__ __launch_bounds__(256) void colsum_kernel(int n) {
    int co = threadIdx.x & 31;          // column octet (8 halfs = 16B)
    int rl = threadIdx.x >> 5;          // row lane 0..7
    float s0[8], s1[8], s2[8];
#pragma unroll
    for (int i = 0; i < 8; i++) { s0[i] = 0.f; s1[i] = 0.f; s2[i] = 0.f; }
    for (int r = blockIdx.x * 8 + rl; r < n; r += gridDim.x * 8) {
        size_t o = (size_t)r * FF + co * 8;
        uint4 ha = *reinterpret_cast<const uint4*>(g_acch + o);
        uint4 hb = *reinterpret_cast<const uint4*>(g_acch + (size_t)NN * FF + o);
        uint4 hm = *reinterpret_cast<const uint4*>(g_mlph + o);
        const uint32_t* pa = &ha.x;
        const uint32_t* pb = &hb.x;
        const uint32_t* pm = &hm.x;
#pragma unroll
        for (int q = 0; q < 4; q++) {
            float2 fa = __half22float2(*reinterpret_cast<const __half2*>(&pa[q]));
            float2 fb = __half22float2(*reinterpret_cast<const __half2*>(&pb[q]));
            float2 fm = __half22float2(*reinterpret_cast<const __half2*>(&pm[q]));
            s0[q * 2] += fmaxf(fa.x, 0.f); s0[q * 2 + 1] += fmaxf(fa.y, 0.f);
            s1[q * 2] += fmaxf(fb.x, 0.f); s1[q * 2 + 1] += fmaxf(fb.y, 0.f);
            s2[q * 2] += fm.x; s2[q * 2 + 1] += fm.y;
        }
    }
    red_add_v4(&g_colsum[co * 8], make_float4(s0[0], s0[1], s0[2], s0[3]));
    red_add_v4(&g_colsum[co * 8 + 4], make_float4(s0[4], s0[5], s0[6], s0[7]));
    red_add_v4(&g_colsum[FF + co * 8], make_float4(s1[0], s1[1], s1[2], s1[3]));
    red_add_v4(&g_colsum[FF + co * 8 + 4], make_float4(s1[4], s1[5], s1[6], s1[7]));
    red_add_v4(&g_colsum[2 * FF + co * 8], make_float4(s2[0], s2[1], s2[2], s2[3]));
    red_add_v4(&g_colsum[2 * FF + co * 8 + 4], make_float4(s2[4], s2[5], s2[6], s2[7]));
}

// ================= tiny attention precompute =================
__global__ __launch_bounds__(256) void attn_small_kernel(
    const float* __restrict__ Wk0, const float* __restrict__ Wk1, const float* __restrict__ Wk2,
    const float* __restrict__ avA, const float* __restrict__ avA2, const float* __restrict__ avM,
    int n)
{
    __shared__ float m[3][FF];
    __shared__ float kk[3][64];
    int tid = threadIdx.x;
    float invn = 1.0f / (float)n;
    m[0][tid] = g_colsum[tid] * invn;
    m[1][tid] = g_colsum[FF + tid] * invn;
    m[2][tid] = g_colsum[2 * FF + tid] * invn;
    __syncthreads();
    int j = tid >> 6;
    int h = tid & 63;
    if (j < 3) {
        const float* Wk = (j == 0) ? Wk0 : ((j == 1) ? Wk1 : Wk2);
        float s = 0.f;
#pragma unroll 8
        for (int c = 0; c < FF; c++) s += m[j][c] * Wk[c * 64 + h];
        kk[j][h] = s;
    }
    __syncthreads();
#pragma unroll
    for (int jj = 0; jj < 3; jj++) {
        const float* av = (jj == 0) ? avA : ((jj == 1) ? avA2 : avM);
        float s = 0.f;
#pragma unroll 8
        for (int hh = 0; hh < 64; hh++) s += av[tid * 64 + hh] * kk[jj][hh];
        g_v[jj * FF + tid] = s;
    }
}

// ================= final: gates + weighted combine (fp16 inputs) =================
__global__ __launch_bounds__(256) void final_kernel(
    const float* __restrict__ attvec, float* __restrict__ out, int n)
{
    __shared__ float sv[3 * FF];
    __shared__ float sav[9];
    int tid = threadIdx.x;
    for (int i = tid; i < 3 * FF; i += 256) sv[i] = g_v[i];
    if (tid < 9) sav[tid] = attvec[tid];
    __syncthreads();

    int warp = tid >> 5;
    int lane = tid & 31;
    int node = blockIdx.x * 8 + warp;
    if (node >= n) return;

    size_t base = (size_t)node * FF;
    uint4 ha = *(reinterpret_cast<const uint4*>(g_acch + base) + lane);
    uint4 hb = *(reinterpret_cast<const uint4*>(g_acch + (size_t)NN * FF + base) + lane);
    uint4 hm = *(reinterpret_cast<const uint4*>(g_mlph + base) + lane);

    float a[8], b[8], mf[8];
    {
        const uint32_t* pa = &ha.x;
        const uint32_t* pb = &hb.x;
        const uint32_t* pm = &hm.x;
#pragma unroll
        for (int q = 0; q < 4; q++) {
            float2 fa = __half22float2(*reinterpret_cast<const __half2*>(&pa[q]));
            float2 fb = __half22float2(*reinterpret_cast<const __half2*>(&pb[q]));
            float2 fm = __half22float2(*reinterpret_cast<const __half2*>(&pm[q]));
            a[q * 2] = fmaxf(fa.x, 0.f); a[q * 2 + 1] = fmaxf(fa.y, 0.f);
            b[q * 2] = fmaxf(fb.x, 0.f); b[q * 2 + 1] = fmaxf(fb.y, 0.f);
            mf[q * 2] = fm.x; mf[q * 2 + 1] = fm.y;
        }
    }

    const float* v0 = sv + lane * 8;
    const float* v1 = sv + FF + lane * 8;
    const float* v2 = sv + 2 * FF + lane * 8;
    float d0 = 0.f, d1 = 0.f, d2 = 0.f;
#pragma unroll
    for (int i = 0; i < 8; i++) {
        d0 = fmaf(a[i], v0[i], d0);
        d1 = fmaf(b[i], v1[i], d1);
        d2 = fmaf(mf[i], v2[i], d2);
    }

#pragma unroll
    for (int o = 16; o > 0; o >>= 1) {
        d0 += __shfl_xor_sync(0xffffffffu, d0, o);
        d1 += __shfl_xor_sync(0xffffffffu, d1, o);
        d2 += __shfl_xor_sync(0xffffffffu, d2, o);
    }

    float s0 = 1.f / (1.f + __expf(-d0));
    float s1 = 1.f / (1.f + __expf(-d1));
    float s2 = 1.f / (1.f + __expf(-d2));
    float zz[3];
#pragma unroll
    for (int i = 0; i < 3; i++)
        zz[i] = (s0 * sav[0 * 3 + i] + s1 * sav[1 * 3 + i] + s2 * sav[2 * 3 + i]) * (1.0f / 3.0f);
    float mx = fmaxf(zz[0], fmaxf(zz[1], zz[2]));
    float e0 = __expf(zz[0] - mx), e1 = __expf(zz[1] - mx), e2 = __expf(zz[2] - mx);
    float inv = 1.f / (e0 + e1 + e2);
    float g0 = 3.f * e0 * inv, g1 = 3.f * e1 * inv, g2 = 3.f * e2 * inv;

    float o0[8];
#pragma unroll
    for (int i = 0; i < 8; i++)
        o0[i] = g0 * a[i] + g1 * b[i] + g2 * mf[i];

    float* po = out + base + lane * 8;
    *reinterpret_cast<float4*>(po) = make_float4(o0[0], o0[1], o0[2], o0[3]);
    *reinterpret_cast<float4*>(po + 4) = make_float4(o0[4], o0[5], o0[6], o0[7]);
}

// ================= launch =================
extern "C" void kernel_launch(void* const* d_in, const int* in_sizes, int n_in,
                              void* d_out, int out_size)
{
    const float* inputx = (const float*)d_in[0];
    const int* row_A = (const int*)d_in[1];
    const int* col_A = (const int*)d_in[2];
    const float* val_A = (const float*)d_in[3];
    const int* row_A2 = (const int*)d_in[4];
    const int* col_A2 = (const int*)d_in[5];
    const float* val_A2 = (const float*)d_in[6];
    const float* weight_A = (const float*)d_in[7];
    const float* weight_A2 = (const float*)d_in[8];
    const float* weight_mlp = (const float*)d_in[9];
    const float* W_k0 = (const float*)d_in[10];
    const float* W_k1 = (const float*)d_in[11];
    const float* W_k2 = (const float*)d_in[12];
    const float* att_vec_A = (const float*)d_in[13];
    const float* att_vec_A2 = (const float*)d_in[14];
    const float* att_vec_mlp = (const float*)d_in[15];
    const float* att_vec = (const float*)d_in[16];
    float* out = (float*)d_out;

    const int n = in_sizes[0] / FF;
    const int E = in_sizes[1];

    // One-time setup on the (non-captured) correctness call.
    static cudaStream_t s2 = nullptr;
    static cudaEvent_t ev_fork = nullptr, ev_join = nullptr;
    static bool configured = false;
    if (!configured) {
        cudaFuncSetAttribute(gemm_mma_kernel, cudaFuncAttributeMaxDynamicSharedMemorySize,
                             GEMM_SMEM_BYTES);
        cudaStreamCreateWithFlags(&s2, cudaStreamNonBlocking);
        cudaEventCreateWithFlags(&ev_fork, cudaEventDisableTiming);
        cudaEventCreateWithFlags(&ev_join, cudaEventDisableTiming);
        configured = true;
    }

    // 0) zero small scratch
    zero_small_kernel<<<(2 * NN + 255) / 256, 256>>>();
    cudaEventRecord(ev_fork, 0);
    cudaStreamWaitEvent(s2, ev_fork, 0);

    // --- stream s2: counting sort of both edge lists by row ---
    {
        dim3 grid(1184, 2);
        hist_kernel<<<grid, 256, 0, s2>>>(row_A, row_A2, E);
        scan_kernel<<<2, 1024, 0, s2>>>(E);
        scatter_kernel<<<grid, 256, 0, s2>>>(row_A, col_A, val_A, row_A2, col_A2, val_A2, E);
    }
    cudaEventRecord(ev_join, s2);

    // --- default stream: converts + GEMM (3 weights, one launch) ---
    convert_x_kernel<<<148 * 20, 256>>>(inputx, n);
    {
        dim3 grid(FF * FF / 256, 3);
        convert_w_kernel<<<grid, 256>>>(weight_A, weight_A2, weight_mlp);
    }
    {
        dim3 grid((n + 127) / 128, FF / 128, 3);
        gemm_mma_kernel<<<grid, 256, GEMM_SMEM_BYTES>>>(n);
    }

    // join: SpMM needs both GEMM output and sorted edges
    cudaStreamWaitEvent(0, ev_join, 0);

    // 4) CSR SpMM: fp16 gather + fp16 result, both matrices concurrent
    {
        dim3 grid((n + 7) / 8, 2);
        spmm_csr_kernel<<<grid, 256>>>(n);
    }

    // 5) column means (fp16 sources)
    colsum_kernel<<<592, 256>>>(n);

    // 6) gate vectors
    attn_small_kernel<<<1, 256>>>(W_k0, W_k1, W_k2, att_vec_A, att_vec_A2, att_vec_mlp, n);

    // 7) fused gating + combine
    final_kernel<<<(n + 7) / 8, 256>>>(att_vec, out, n);
}

// round 14
// speedup vs baseline: 1.1193x; 1.1193x over previous
#include <cuda_runtime.h>
#include <cuda_fp16.h>
#include <cstdint>
#include <cstdio>

#define NN 100000
#define FF 256
#define EMAX 3200000

typedef unsigned long long ull;

// ================= scratch (device globals; no allocation allowed) =================
__device__ __align__(256) __half g_xwh[2 * (size_t)NN * FF];  // X@W_A, X@W_A2 fp16 (SpMM gather)
__device__ float g_mlp[(size_t)NN * FF];       // relu(X @ W_mlp) fp32
__device__ float g_acc0[(size_t)NN * FF];      // spmm result A
__device__ float g_acc1[(size_t)NN * FF];      // spmm result A2
__device__ float g_colsum[3 * FF];
__device__ float g_v[3 * FF];
__device__ __align__(256) __half g_xh[(size_t)NN * FF];   // fp16(X)
__device__ __align__(256) __half g_wth[3 * FF * FF];      // fp16(W^T)
__device__ __align__(256) __half g_wtl[3 * FF * FF];      // fp16(W^T - fp16(W^T))
// counting-sort scratch
__device__ int g_cnt[2 * NN];
__device__ int g_ptr[2 * (NN + 1)];
__device__ int g_off[2 * NN];
__device__ __align__(256) ull g_edges[2 * (size_t)EMAX];  // packed (val<<32 | col), row-sorted

// ================= helpers =================
__device__ __forceinline__ uint32_t smem_u32(const void* p) {
    uint32_t a;
    asm("{ .reg .u64 t; cvta.to.shared.u64 t, %1; cvt.u32.u64 %0, t; }" : "=r"(a) : "l"(p));
    return a;
}
__device__ __forceinline__ void cp_async16(uint32_t dst, const void* src, uint32_t bytes) {
    asm volatile("cp.async.ca.shared.global [%0], [%1], 16, %2;"
                 :: "r"(dst), "l"(src), "r"(bytes) : "memory");
}
#define CP_COMMIT() asm volatile("cp.async.commit_group;" ::: "memory")
#define CP_WAIT0()  asm volatile("cp.async.wait_group 0;" ::: "memory")
#define CP_WAIT1()  asm volatile("cp.async.wait_group 1;" ::: "memory")

__device__ __forceinline__ void ldsm_x4(uint32_t& r0, uint32_t& r1, uint32_t& r2, uint32_t& r3,
                                        uint32_t addr) {
    asm volatile("ldmatrix.sync.aligned.m8n8.x4.shared.b16 {%0,%1,%2,%3}, [%4];"
                 : "=r"(r0), "=r"(r1), "=r"(r2), "=r"(r3) : "r"(addr));
}
__device__ __forceinline__ void ldsm_x2(uint32_t& r0, uint32_t& r1, uint32_t addr) {
    asm volatile("ldmatrix.sync.aligned.m8n8.x2.shared.b16 {%0,%1}, [%2];"
                 : "=r"(r0), "=r"(r1) : "r"(addr));
}
__device__ __forceinline__ void mma_f16(float* d, const uint32_t* a, const uint32_t* b) {
    asm volatile(
        "mma.sync.aligned.m16n8k16.row.col.f32.f16.f16.f32 "
        "{%0,%1,%2,%3}, {%4,%5,%6,%7}, {%8,%9}, {%0,%1,%2,%3};"
        : "+f"(d[0]), "+f"(d[1]), "+f"(d[2]), "+f"(d[3])
        : "r"(a[0]), "r"(a[1]), "r"(a[2]), "r"(a[3]), "r"(b[0]), "r"(b[1]));
}
__device__ __forceinline__ void red_add_v4(float* p, float4 v) {
    asm volatile("red.relaxed.gpu.global.add.v4.f32 [%0], {%1,%2,%3,%4};"
                 :: "l"(p), "f"(v.x), "f"(v.y), "f"(v.z), "f"(v.w) : "memory");
}

// ================= zero histograms + colsum =================
__global__ void zero_small_kernel() {
    int t = blockIdx.x * blockDim.x + threadIdx.x;
    if (t < 2 * NN) g_cnt[t] = 0;
    if (t < 3 * FF) g_colsum[t] = 0.f;
}

// ================= convert X -> fp16 =================
__global__ __launch_bounds__(256) void convert_x_kernel(const float* __restrict__ X, int n) {
    size_t total4 = (size_t)n * (FF / 4);
    size_t stride = (size_t)gridDim.x * blockDim.x;
    for (size_t i4 = (size_t)blockIdx.x * blockDim.x + threadIdx.x; i4 < total4; i4 += stride) {
        float4 x = reinterpret_cast<const float4*>(X)[i4];
        __half2 h0 = __float22half2_rn(make_float2(x.x, x.y));
        __half2 h1 = __float22half2_rn(make_float2(x.z, x.w));
        size_t i = i4 * 4;
        reinterpret_cast<__half2*>(g_xh + i)[0] = h0;
        reinterpret_cast<__half2*>(g_xh + i)[1] = h1;
    }
}

// ================= transpose + convert W -> fp16 hi/lo =================
__global__ __launch_bounds__(256) void convert_w_kernel(
    const float* __restrict__ W0, const float* __restrict__ W1, const float* __restrict__ W2)
{
    int z = blockIdx.y;
    const float* W = (z == 0) ? W0 : ((z == 1) ? W1 : W2);
    int t = blockIdx.x * 256 + threadIdx.x;
    int k = t & 255;
    int nn = t >> 8;
    float x = W[k * 256 + nn];
    __half h = __float2half_rn(x);
    __half l = __float2half_rn(x - __half2float(h));
    g_wth[(size_t)z * 65536 + nn * 256 + k] = h;
    g_wtl[(size_t)z * 65536 + nn * 256 + k] = l;
}

// ================= HMMA GEMM (2-term fp16 split: Xh@Whi + Xh@Wlo) ================
// z<2 -> fp16 xw output; z==2 -> relu fp32 mlp output.
static constexpr int TSTRIDE = 40;
static constexpr int TILE_B = 128 * TSTRIDE * 2;
static constexpr int STAGE_B = 3 * TILE_B;          // A, Bhi, Blo
static constexpr uint32_t GEMM_SMEM_BYTES = 2 * STAGE_B + 256;

__global__ __launch_bounds__(256, 1) void gemm_mma_kernel(int n)
{
    extern __shared__ char dynsmem[];
    uint32_t raw = smem_u32(dynsmem);
    uint32_t base = (raw + 127) & ~127u;

    const int z = blockIdx.z;
    const __half* __restrict__ WH = g_wth + (size_t)z * 65536;
    const __half* __restrict__ WL = g_wtl + (size_t)z * 65536;

    const int row0 = blockIdx.x * 128;
    const int col0 = blockIdx.y * 128;
    const int tid = threadIdx.x;
    const int wid = tid >> 5;
    const int lane = tid & 31;
    const int warp_m = wid & 1;
    const int warp_n = wid >> 1;

    const uint32_t AT = 0, BH = TILE_B, BL = 2 * TILE_B;

    auto load_chunk = [&](int s, int c) {
        const uint32_t st = base + s * STAGE_B;
        const int k0 = c * 32;
#pragma unroll
        for (int it = 0; it < 2; it++) {
            int idx = tid + it * 256;
            int r = idx >> 2;
            int q = idx & 3;
            uint32_t dsto = (uint32_t)(r * (TSTRIDE * 2) + q * 16);
            int gr = row0 + r;
            uint32_t sz = (gr < n) ? 16u : 0u;
            const __half* sa = g_xh + (size_t)(gr < n ? gr : 0) * FF + k0 + q * 8;
            cp_async16(st + AT + dsto, sa, sz);
            int nr = col0 + r;
            cp_async16(st + BH + dsto, WH + (size_t)nr * FF + k0 + q * 8, 16);
            cp_async16(st + BL + dsto, WL + (size_t)nr * FF + k0 + q * 8, 16);
        }
        CP_COMMIT();
    };

    float acc[4][4][4];
#pragma unroll
    for (int i = 0; i < 4; i++)
#pragma unroll
        for (int j = 0; j < 4; j++)
#pragma unroll
            for (int q = 0; q < 4; q++) acc[i][j][q] = 0.f;

    const uint32_t a_off = (uint32_t)((warp_m * 64 + (lane & 15)) * (TSTRIDE * 2) + (lane >> 4) * 16);
    const uint32_t b_off = (uint32_t)((warp_n * 32 + (lane & 7)) * (TSTRIDE * 2) + ((lane >> 3) & 1) * 16);

    load_chunk(0, 0);

    for (int c = 0; c < 8; c++) {
        const int s = c & 1;
        if (c < 7) load_chunk(s ^ 1, c + 1);
        if (c < 7) { CP_WAIT1(); } else { CP_WAIT0(); }
        __syncthreads();

        const uint32_t st = base + s * STAGE_B;
#pragma unroll
        for (int ks = 0; ks < 2; ks++) {
            uint32_t ah[4][4], bh[4][2], bl[4][2];
#pragma unroll
            for (int mt = 0; mt < 4; mt++) {
                uint32_t ao = st + a_off + (uint32_t)(mt * 16 * TSTRIDE * 2 + ks * 32);
                ldsm_x4(ah[mt][0], ah[mt][1], ah[mt][2], ah[mt][3], ao + AT);
            }
#pragma unroll
            for (int nt = 0; nt < 4; nt++) {
                uint32_t bo = st + b_off + (uint32_t)(nt * 8 * TSTRIDE * 2 + ks * 32);
                ldsm_x2(bh[nt][0], bh[nt][1], bo + BH);
                ldsm_x2(bl[nt][0], bl[nt][1], bo + BL);
            }
#pragma unroll
            for (int mt = 0; mt < 4; mt++)
#pragma unroll
                for (int nt = 0; nt < 4; nt++) {
                    mma_f16(acc[mt][nt], ah[mt], bh[nt]);   // Xh @ Whi
                    mma_f16(acc[mt][nt], ah[mt], bl[nt]);   // Xh @ Wlo
                }
        }
        __syncthreads();
    }

    const int er = lane >> 2;
    const int ec = (lane & 3) * 2;
#pragma unroll
    for (int mt = 0; mt < 4; mt++) {
#pragma unroll
        for (int nt = 0; nt < 4; nt++) {
            int col = col0 + warp_n * 32 + nt * 8 + ec;
            int r1 = row0 + warp_m * 64 + mt * 16 + er;
            int r2 = r1 + 8;
            float2 v1 = make_float2(acc[mt][nt][0], acc[mt][nt][1]);
            float2 v2 = make_float2(acc[mt][nt][2], acc[mt][nt][3]);
            if (z == 2) {
                v1.x = fmaxf(v1.x, 0.f); v1.y = fmaxf(v1.y, 0.f);
                v2.x = fmaxf(v2.x, 0.f); v2.y = fmaxf(v2.y, 0.f);
                if (r1 < n) *reinterpret_cast<float2*>(g_mlp + (size_t)r1 * FF + col) = v1;
                if (r2 < n) *reinterpret_cast<float2*>(g_mlp + (size_t)r2 * FF + col) = v2;
            } else {
                __half* outh = g_xwh + (size_t)z * NN * FF;
                __half2 h1 = __float22half2_rn(v1);
                __half2 h2 = __float22half2_rn(v2);
                if (r1 < n) *reinterpret_cast<__half2*>(outh + (size_t)r1 * FF + col) = h1;
                if (r2 < n) *reinterpret_cast<__half2*>(outh + (size_t)r2 * FF + col) = h2;
            }
        }
    }
}

// ================= counting sort: histogram =================
__global__ __launch_bounds__(256) void hist_kernel(
    const int* __restrict__ rowA, const int* __restrict__ rowB, int E)
{
    const int m = blockIdx.y;
    const int* __restrict__ row = (m == 0) ? rowA : rowB;
    int* cnt = g_cnt + m * NN;
    int stride = gridDim.x * blockDim.x;
    for (int i = blockIdx.x * blockDim.x + threadIdx.x; i < E; i += stride)
        atomicAdd(&cnt[row[i]], 1);
}

// ================= counting sort: exclusive scan (1 block per matrix) ============
__global__ __launch_bounds__(1024) void scan_kernel(int E) {
    const int m = blockIdx.x;
    const int* cnt = g_cnt + m * NN;
    int* ptr = g_ptr + m * (NN + 1);
    int* off = g_off + m * NN;
    __shared__ int wsum[32];
    __shared__ int carry_s;
    int tid = threadIdx.x;
    int lane = tid & 31, wid = tid >> 5;
    if (tid == 0) carry_s = 0;
    __syncthreads();
    for (int basei = 0; basei < NN; basei += 1024) {
        int i = basei + tid;
        int v = (i < NN) ? cnt[i] : 0;
        int x = v;
#pragma unroll
        for (int o = 1; o < 32; o <<= 1) {
            int y = __shfl_up_sync(0xffffffffu, x, o);
            if (lane >= o) x += y;
        }
        if (lane == 31) wsum[wid] = x;
        __syncthreads();
        if (wid == 0) {
            int s = wsum[lane];
#pragma unroll
            for (int o = 1; o < 32; o <<= 1) {
                int y = __shfl_up_sync(0xffffffffu, s, o);
                if (lane >= o) s += y;
            }
            wsum[lane] = s;
        }
        __syncthreads();
        int incl = x + (wid > 0 ? wsum[wid - 1] : 0);
        int excl = incl - v + carry_s;
        if (i < NN) { ptr[i] = excl; off[i] = excl; }
        __syncthreads();
        if (tid == 1023) carry_s += incl;
        __syncthreads();
    }
    if (threadIdx.x == 0) ptr[NN] = E;
}

// ================= counting sort: scatter packed (val,col) =================
__global__ __launch_bounds__(256) void scatter_kernel(
    const int* __restrict__ rowA, const int* __restrict__ colA, const float* __restrict__ valA,
    const int* __restrict__ rowB, const int* __restrict__ colB, const float* __restrict__ valB,
    int E)
{
    const int m = blockIdx.y;
    const int* __restrict__ row = (m == 0) ? rowA : rowB;
    const int* __restrict__ col = (m == 0) ? colA : colB;
    const float* __restrict__ val = (m == 0) ? valA : valB;
    int* off = g_off + m * NN;
    ull* edges = g_edges + (size_t)m * EMAX;
    int stride = gridDim.x * blockDim.x;
    for (int i = blockIdx.x * blockDim.x + threadIdx.x; i < E; i += stride) {
        int r = row[i];
        int pos = atomicAdd(&off[r], 1);
        ull e = ((ull)__float_as_uint(val[i]) << 32) | (uint32_t)col[i];
        edges[pos] = e;
    }
}

// ================= CSR SpMM: fp16 gather, fp32 result, one warp per row =========
__global__ __launch_bounds__(256) void spmm_csr_kernel(int n)
{
    const int m = blockIdx.y;
    const __half* __restrict__ x = g_xwh + (size_t)m * NN * FF;
    float* __restrict__ acc = (m == 0) ? g_acc0 : g_acc1;
    const ull* __restrict__ edges = g_edges + (size_t)m * EMAX;
    const int* __restrict__ ptr = g_ptr + m * (NN + 1);

    int warp = threadIdx.x >> 5;
    int lane = threadIdx.x & 31;
    int r = blockIdx.x * 8 + warp;
    if (r >= n) return;

    int s = ptr[r], e = ptr[r + 1];
    float a[8];
#pragma unroll
    for (int i = 0; i < 8; i++) a[i] = 0.f;

    for (int b = s; b < e; b += 32) {
        int cntb = min(32, e - b);
        ull my = (b + lane < e) ? __ldg(edges + b + lane) : 0ull;
        for (int j = 0; j < cntb; j++) {
            ull ed = __shfl_sync(0xffffffffu, my, j);
            int c = (int)(uint32_t)ed;
            float v = __uint_as_float((uint32_t)(ed >> 32));
            uint4 h = __ldg(reinterpret_cast<const uint4*>(x + (size_t)c * FF) + lane);
            float2 f0 = __half22float2(*reinterpret_cast<__half2*>(&h.x));
            float2 f1 = __half22float2(*reinterpret_cast<__half2*>(&h.y));
            float2 f2 = __half22float2(*reinterpret_cast<__half2*>(&h.z));
            float2 f3 = __half22float2(*reinterpret_cast<__half2*>(&h.w));
            a[0] = fmaf(v, f0.x, a[0]); a[1] = fmaf(v, f0.y, a[1]);
            a[2] = fmaf(v, f1.x, a[2]); a[3] = fmaf(v, f1.y, a[3]);
            a[4] = fmaf(v, f2.x, a[4]); a[5] = fmaf(v, f2.y, a[5]);
            a[6] = fmaf(v, f3.x, a[6]); a[7] = fmaf(v, f3.y, a[7]);
        }
    }
    float* dst = acc + (size_t)r * FF + lane * 8;
    *reinterpret_cast<float4*>(dst) = make_float4(a[0], a[1], a[2], a[3]);
    *reinterpret_cast<float4*>(dst + 4) = make_float4(a[4], a[5], a[6], a[7]);
}

// ================= column sums (vectorized float4) =================
__global__ __launch_bounds__(256) void colsum_kernel(int n) {
    int c4 = threadIdx.x & 63;
    int rl = threadIdx.x >> 6;
    float4 s0 = make_float4(0.f, 0.f, 0.f, 0.f);
    float4 s1 = s0, s2 = s0;
    for (int r = blockIdx.x * 4 + rl; r < n; r += gridDim.x * 4) {
        size_t o = (size_t)r * (FF / 4) + c4;
        float4 a = reinterpret_cast<const float4*>(g_acc0)[o];
        float4 b = reinterpret_cast<const float4*>(g_acc1)[o];
        float4 mm = reinterpret_cast<const float4*>(g_mlp)[o];
        s0.x += fmaxf(a.x, 0.f); s0.y += fmaxf(a.y, 0.f); s0.z += fmaxf(a.z, 0.f); s0.w += fmaxf(a.w, 0.f);
        s1.x += fmaxf(b.x, 0.f); s1.y += fmaxf(b.y, 0.f); s1.z += fmaxf(b.z, 0.f); s1.w += fmaxf(b.w, 0.f);
        s2.x += mm.x; s2.y += mm.y; s2.z += mm.z; s2.w += mm.w;
    }
    red_add_v4(&g_colsum[c4 * 4], s0);
    red_add_v4(&g_colsum[FF + c4 * 4], s1);
    red_add_v4(&g_colsum[2 * FF + c4 * 4], s2);
}

// ================= tiny attention precompute =================
__global__ __launch_bounds__(256) void attn_small_kernel(
    const float* __restrict__ Wk0, const float* __restrict__ Wk1, const float* __restrict__ Wk2,
    const float* __restrict__ avA, const float* __restrict__ avA2, const float* __restrict__ avM,
    int n)
{
    __shared__ float m[3][FF];
    __shared__ float kk[3][64];
    int tid = threadIdx.x;
    float invn = 1.0f / (float)n;
    m[0][tid] = g_colsum[tid] * invn;
    m[1][tid] = g_colsum[FF + tid] * invn;
    m[2][tid] = g_colsum[2 * FF + tid] * invn;
    __syncthreads();
    int j = tid >> 6;
    int h = tid & 63;
    if (j < 3) {
        const float* Wk = (j == 0) ? Wk0 : ((j == 1) ? Wk1 : Wk2);
        float s = 0.f;
#pragma unroll 8
        for (int c = 0; c < FF; c++) s += m[j][c] * Wk[c * 64 + h];
        kk[j][h] = s;
    }
    __syncthreads();
#pragma unroll
    for (int jj = 0; jj < 3; jj++) {
        const float* av = (jj == 0) ? avA : ((jj == 1) ? avA2 : avM);
        float s = 0.f;
#pragma unroll 8
        for (int hh = 0; hh < 64; hh++) s += av[tid * 64 + hh] * kk[jj][hh];
        g_v[jj * FF + tid] = s;
    }
}

// ================= final: gates + weighted combine =================
__global__ __launch_bounds__(256) void final_kernel(
    const float* __restrict__ attvec, float* __restrict__ out, int n)
{
    __shared__ float sv[3 * FF];
    __shared__ float sav[9];
    int tid = threadIdx.x;
    for (int i = tid; i < 3 * FF; i += 256) sv[i] = g_v[i];
    if (tid < 9) sav[tid] = attvec[tid];
    __syncthreads();

    int warp = tid >> 5;
    int lane = tid & 31;
    int node = blockIdx.x * 8 + warp;
    if (node >= n) return;

    size_t base = (size_t)node * FF;
    const float4* pa = reinterpret_cast<const float4*>(g_acc0 + base);
    const float4* pb = reinterpret_cast<const float4*>(g_acc1 + base);
    const float4* pm = reinterpret_cast<const float4*>(g_mlp + base);

    float4 a0 = pa[lane], a1 = pa[lane + 32];
    float4 b0 = pb[lane], b1 = pb[lane + 32];
    float4 m0 = pm[lane], m1 = pm[lane + 32];
    a0.x = fmaxf(a0.x, 0.f); a0.y = fmaxf(a0.y, 0.f); a0.z = fmaxf(a0.z, 0.f); a0.w = fmaxf(a0.w, 0.f);
    a1.x = fmaxf(a1.x, 0.f); a1.y = fmaxf(a1.y, 0.f); a1.z = fmaxf(a1.z, 0.f); a1.w = fmaxf(a1.w, 0.f);
    b0.x = fmaxf(b0.x, 0.f); b0.y = fmaxf(b0.y, 0.f); b0.z = fmaxf(b0.z, 0.f); b0.w = fmaxf(b0.w, 0.f);
    b1.x = fmaxf(b1.x, 0.f); b1.y = fmaxf(b1.y, 0.f); b1.z = fmaxf(b1.z, 0.f); b1.w = fmaxf(b1.w, 0.f);

    const float4* v0p = reinterpret_cast<const float4*>(sv);
    const float4* v1p = reinterpret_cast<const float4*>(sv + FF);
    const float4* v2p = reinterpret_cast<const float4*>(sv + 2 * FF);
    float4 v00 = v0p[lane], v01 = v0p[lane + 32];
    float4 v10 = v1p[lane], v11 = v1p[lane + 32];
    float4 v20 = v2p[lane], v21 = v2p[lane + 32];

    float d0 = a0.x * v00.x + a0.y * v00.y + a0.z * v00.z + a0.w * v00.w
             + a1.x * v01.x + a1.y * v01.y + a1.z * v01.z + a1.w * v01.w;
    float d1 = b0.x * v10.x + b0.y * v10.y + b0.z * v10.z + b0.w * v10.w
             + b1.x * v11.x + b1.y * v11.y + b1.z * v11.z + b1.w * v11.w;
    float d2 = m0.x * v20.x + m0.y * v20.y + m0.z * v20.z + m0.w * v20.w
             + m1.x * v21.x + m1.y * v21.y + m1.z * v21.z + m1.w * v21.w;

#pragma unroll
    for (int o = 16; o > 0; o >>= 1) {
        d0 += __shfl_xor_sync(0xffffffffu, d0, o);
        d1 += __shfl_xor_sync(0xffffffffu, d1, o);
        d2 += __shfl_xor_sync(0xffffffffu, d2, o);
    }

    float s0 = 1.f / (1.f + __expf(-d0));
    float s1 = 1.f / (1.f + __expf(-d1));
    float s2 = 1.f / (1.f + __expf(-d2));
    float zz[3];
#pragma unroll
    for (int i = 0; i < 3; i++)
        zz[i] = (s0 * sav[0 * 3 + i] + s1 * sav[1 * 3 + i] + s2 * sav[2 * 3 + i]) * (1.0f / 3.0f);
    float mx = fmaxf(zz[0], fmaxf(zz[1], zz[2]));
    float e0 = __expf(zz[0] - mx), e1 = __expf(zz[1] - mx), e2 = __expf(zz[2] - mx);
    float inv = 1.f / (e0 + e1 + e2);
    float g0 = 3.f * e0 * inv, g1 = 3.f * e1 * inv, g2 = 3.f * e2 * inv;

    float4 o0, o1;
    o0.x = g0 * a0.x + g1 * b0.x + g2 * m0.x;
    o0.y = g0 * a0.y + g1 * b0.y + g2 * m0.y;
    o0.z = g0 * a0.z + g1 * b0.z + g2 * m0.z;
    o0.w = g0 * a0.w + g1 * b0.w + g2 * m0.w;
    o1.x = g0 * a1.x + g1 * b1.x + g2 * m1.x;
    o1.y = g0 * a1.y + g1 * b1.y + g2 * m1.y;
    o1.z = g0 * a1.z + g1 * b1.z + g2 * m1.z;
    o1.w = g0 * a1.w + g1 * b1.w + g2 * m1.w;

    float4* po = reinterpret_cast<float4*>(out + base);
    po[lane] = o0;
    po[lane + 32] = o1;
}

// ================= launch =================
extern "C" void kernel_launch(void* const* d_in, const int* in_sizes, int n_in,
                              void* d_out, int out_size)
{
    const float* inputx = (const float*)d_in[0];
    const int* row_A = (const int*)d_in[1];
    const int* col_A = (const int*)d_in[2];
    const float* val_A = (const float*)d_in[3];
    const int* row_A2 = (const int*)d_in[4];
    const int* col_A2 = (const int*)d_in[5];
    const float* val_A2 = (const float*)d_in[6];
    const float* weight_A = (const float*)d_in[7];
    const float* weight_A2 = (const float*)d_in[8];
    const float* weight_mlp = (const float*)d_in[9];
    const float* W_k0 = (const float*)d_in[10];
    const float* W_k1 = (const float*)d_in[11];
    const float* W_k2 = (const float*)d_in[12];
    const float* att_vec_A = (const float*)d_in[13];
    const float* att_vec_A2 = (const float*)d_in[14];
    const float* att_vec_mlp = (const float*)d_in[15];
    const float* att_vec = (const float*)d_in[16];
    float* out = (float*)d_out;

    const int n = in_sizes[0] / FF;
    const int E = in_sizes[1];

    // One-time setup on the (non-captured) correctness call.
    static cudaStream_t s2 = nullptr;
    static cudaEvent_t ev_fork = nullptr, ev_join = nullptr;
    static bool configured = false;
    if (!configured) {
        cudaFuncSetAttribute(gemm_mma_kernel, cudaFuncAttributeMaxDynamicSharedMemorySize,
                             GEMM_SMEM_BYTES);
        cudaStreamCreateWithFlags(&s2, cudaStreamNonBlocking);
        cudaEventCreateWithFlags(&ev_fork, cudaEventDisableTiming);
        cudaEventCreateWithFlags(&ev_join, cudaEventDisableTiming);
        configured = true;
    }

    // 0) zero small scratch
    zero_small_kernel<<<(2 * NN + 255) / 256, 256>>>();
    cudaEventRecord(ev_fork, 0);
    cudaStreamWaitEvent(s2, ev_fork, 0);

    // --- stream s2: counting sort of both edge lists by row ---
    {
        dim3 grid(1184, 2);
        hist_kernel<<<grid, 256, 0, s2>>>(row_A, row_A2, E);
        scan_kernel<<<2, 1024, 0, s2>>>(E);
        scatter_kernel<<<grid, 256, 0, s2>>>(row_A, col_A, val_A, row_A2, col_A2, val_A2, E);
    }
    cudaEventRecord(ev_join, s2);

    // --- default stream: converts + GEMM (3 weights, one launch) ---
    convert_x_kernel<<<148 * 20, 256>>>(inputx, n);
    {
        dim3 grid(FF * FF / 256, 3);
        convert_w_kernel<<<grid, 256>>>(weight_A, weight_A2, weight_mlp);
    }
    {
        dim3 grid((n + 127) / 128, FF / 128, 3);
        gemm_mma_kernel<<<grid, 256, GEMM_SMEM_BYTES>>>(n);
    }

    // join: SpMM needs both GEMM output and sorted edges
    cudaStreamWaitEvent(0, ev_join, 0);

    // 4) CSR SpMM: fp16 gather, both matrices concurrent (102MB L2-resident)
    {
        dim3 grid((n + 7) / 8, 2);
        spmm_csr_kernel<<<grid, 256>>>(n);
    }

    // 5) column means (vectorized)
    colsum_kernel<<<1184, 256>>>(n);

    // 6) gate vectors
    attn_small_kernel<<<1, 256>>>(W_k0, W_k1, W_k2, att_vec_A, att_vec_A2, att_vec_mlp, n);

    // 7) fused gating + combine
    final_kernel<<<(n + 7) / 8, 256>>>(att_vec, out, n);
}

// round 15
// speedup vs baseline: 1.1896x; 1.0628x over previous
#include <cuda_runtime.h>
#include <cuda_fp16.h>
#include <cstdint>
#include <cstdio>

#define NN 100000
#define FF 256
#define EMAX 3200000

typedef unsigned long long ull;

// ================= scratch (device globals; no allocation allowed) =================
__device__ __align__(256) __half g_xwh[2 * (size_t)NN * FF];  // X@W_A, X@W_A2 fp16 (SpMM gather)
__device__ float g_mlp[(size_t)NN * FF];       // relu(X @ W_mlp) fp32
__device__ float g_acc0[(size_t)NN * FF];      // spmm result A
__device__ float g_acc1[(size_t)NN * FF];      // spmm result A2
__device__ float g_colsum[3 * FF];
__device__ float g_v[3 * FF];
__device__ __align__(256) __half g_xh[(size_t)NN * FF];   // fp16(X)
__device__ __align__(256) __half g_wth[3 * FF * FF];      // fp16(W^T)
__device__ __align__(256) __half g_wtl[3 * FF * FF];      // fp16(W^T - fp16(W^T))
// counting-sort scratch
__device__ int g_cnt[2 * NN];
__device__ int g_ptr[2 * (NN + 1)];
__device__ int g_off[2 * NN];
__device__ __align__(256) ull g_edges[2 * (size_t)EMAX];  // packed (val<<32 | col), row-sorted

// ================= helpers =================
__device__ __forceinline__ uint32_t smem_u32(const void* p) {
    uint32_t a;
    asm("{ .reg .u64 t; cvta.to.shared.u64 t, %1; cvt.u32.u64 %0, t; }" : "=r"(a) : "l"(p));
    return a;
}
__device__ __forceinline__ void cp_async16(uint32_t dst, const void* src, uint32_t bytes) {
    asm volatile("cp.async.ca.shared.global [%0], [%1], 16, %2;"
                 :: "r"(dst), "l"(src), "r"(bytes) : "memory");
}
#define CP_COMMIT() asm volatile("cp.async.commit_group;" ::: "memory")
#define CP_WAIT0()  asm volatile("cp.async.wait_group 0;" ::: "memory")
#define CP_WAIT1()  asm volatile("cp.async.wait_group 1;" ::: "memory")

__device__ __forceinline__ void ldsm_x4(uint32_t& r0, uint32_t& r1, uint32_t& r2, uint32_t& r3,
                                        uint32_t addr) {
    asm volatile("ldmatrix.sync.aligned.m8n8.x4.shared.b16 {%0,%1,%2,%3}, [%4];"
                 : "=r"(r0), "=r"(r1), "=r"(r2), "=r"(r3) : "r"(addr));
}
__device__ __forceinline__ void ldsm_x2(uint32_t& r0, uint32_t& r1, uint32_t addr) {
    asm volatile("ldmatrix.sync.aligned.m8n8.x2.shared.b16 {%0,%1}, [%2];"
                 : "=r"(r0), "=r"(r1) : "r"(addr));
}
__device__ __forceinline__ void mma_f16(float* d, const uint32_t* a, const uint32_t* b) {
    asm volatile(
        "mma.sync.aligned.m16n8k16.row.col.f32.f16.f16.f32 "
        "{%0,%1,%2,%3}, {%4,%5,%6,%7}, {%8,%9}, {%0,%1,%2,%3};"
        : "+f"(d[0]), "+f"(d[1]), "+f"(d[2]), "+f"(d[3])
        : "r"(a[0]), "r"(a[1]), "r"(a[2]), "r"(a[3]), "r"(b[0]), "r"(b[1]));
}
__device__ __forceinline__ void red_add_v4(float* p, float4 v) {
    asm volatile("red.relaxed.gpu.global.add.v4.f32 [%0], {%1,%2,%3,%4};"
                 :: "l"(p), "f"(v.x), "f"(v.y), "f"(v.z), "f"(v.w) : "memory");
}

// ================= zero histograms + colsum =================
__global__ void zero_small_kernel() {
    int t = blockIdx.x * blockDim.x + threadIdx.x;
    if (t < 2 * NN) g_cnt[t] = 0;
    if (t < 3 * FF) g_colsum[t] = 0.f;
}

// ================= convert X -> fp16 =================
__global__ __launch_bounds__(256) void convert_x_kernel(const float* __restrict__ X, int n) {
    size_t total4 = (size_t)n * (FF / 4);
    size_t stride = (size_t)gridDim.x * blockDim.x;
    for (size_t i4 = (size_t)blockIdx.x * blockDim.x + threadIdx.x; i4 < total4; i4 += stride) {
        float4 x = reinterpret_cast<const float4*>(X)[i4];
        __half2 h0 = __float22half2_rn(make_float2(x.x, x.y));
        __half2 h1 = __float22half2_rn(make_float2(x.z, x.w));
        size_t i = i4 * 4;
        reinterpret_cast<__half2*>(g_xh + i)[0] = h0;
        reinterpret_cast<__half2*>(g_xh + i)[1] = h1;
    }
}

// ================= transpose + convert W -> fp16 hi/lo =================
__global__ __launch_bounds__(256) void convert_w_kernel(
    const float* __restrict__ W0, const float* __restrict__ W1, const float* __restrict__ W2)
{
    int z = blockIdx.y;
    const float* W = (z == 0) ? W0 : ((z == 1) ? W1 : W2);
    int t = blockIdx.x * 256 + threadIdx.x;
    int k = t & 255;
    int nn = t >> 8;
    float x = W[k * 256 + nn];
    __half h = __float2half_rn(x);
    __half l = __float2half_rn(x - __half2float(h));
    g_wth[(size_t)z * 65536 + nn * 256 + k] = h;
    g_wtl[(size_t)z * 65536 + nn * 256 + k] = l;
}

// ================= HMMA GEMM (2-term fp16 split: Xh@Whi + Xh@Wlo) ================
// z<2 -> fp16 xw output; z==2 -> relu fp32 mlp output.
// __launch_bounds__(256,2): cap regs at 128 so 2 CTAs co-reside per SM and
// hide syncthreads/epilogue tensor-idle gaps.
static constexpr int TSTRIDE = 40;
static constexpr int TILE_B = 128 * TSTRIDE * 2;
static constexpr int STAGE_B = 3 * TILE_B;          // A, Bhi, Blo
static constexpr uint32_t GEMM_SMEM_BYTES = 2 * STAGE_B + 256;

__global__ __launch_bounds__(256, 2) void gemm_mma_kernel(int n)
{
    extern __shared__ char dynsmem[];
    uint32_t raw = smem_u32(dynsmem);
    uint32_t base = (raw + 127) & ~127u;

    const int z = blockIdx.z;
    const __half* __restrict__ WH = g_wth + (size_t)z * 65536;
    const __half* __restrict__ WL = g_wtl + (size_t)z * 65536;

    const int row0 = blockIdx.x * 128;
    const int col0 = blockIdx.y * 128;
    const int tid = threadIdx.x;
    const int wid = tid >> 5;
    const int lane = tid & 31;
    const int warp_m = wid & 1;
    const int warp_n = wid >> 1;

    const uint32_t AT = 0, BH = TILE_B, BL = 2 * TILE_B;

    auto load_chunk = [&](int s, int c) {
        const uint32_t st = base + s * STAGE_B;
        const int k0 = c * 32;
#pragma unroll
        for (int it = 0; it < 2; it++) {
            int idx = tid + it * 256;
            int r = idx >> 2;
            int q = idx & 3;
            uint32_t dsto = (uint32_t)(r * (TSTRIDE * 2) + q * 16);
            int gr = row0 + r;
            uint32_t sz = (gr < n) ? 16u : 0u;
            const __half* sa = g_xh + (size_t)(gr < n ? gr : 0) * FF + k0 + q * 8;
            cp_async16(st + AT + dsto, sa, sz);
            int nr = col0 + r;
            cp_async16(st + BH + dsto, WH + (size_t)nr * FF + k0 + q * 8, 16);
            cp_async16(st + BL + dsto, WL + (size_t)nr * FF + k0 + q * 8, 16);
        }
        CP_COMMIT();
    };

    float acc[4][4][4];
#pragma unroll
    for (int i = 0; i < 4; i++)
#pragma unroll
        for (int j = 0; j < 4; j++)
#pragma unroll
            for (int q = 0; q < 4; q++) acc[i][j][q] = 0.f;

    const uint32_t a_off = (uint32_t)((warp_m * 64 + (lane & 15)) * (TSTRIDE * 2) + (lane >> 4) * 16);
    const uint32_t b_off = (uint32_t)((warp_n * 32 + (lane & 7)) * (TSTRIDE * 2) + ((lane >> 3) & 1) * 16);

    load_chunk(0, 0);

    for (int c = 0; c < 8; c++) {
        const int s = c & 1;
        if (c < 7) load_chunk(s ^ 1, c + 1);
        if (c < 7) { CP_WAIT1(); } else { CP_WAIT0(); }
        __syncthreads();

        const uint32_t st = base + s * STAGE_B;
#pragma unroll
        for (int ks = 0; ks < 2; ks++) {
            uint32_t ah[4][4], bh[4][2], bl[4][2];
#pragma unroll
            for (int mt = 0; mt < 4; mt++) {
                uint32_t ao = st + a_off + (uint32_t)(mt * 16 * TSTRIDE * 2 + ks * 32);
                ldsm_x4(ah[mt][0], ah[mt][1], ah[mt][2], ah[mt][3], ao + AT);
            }
#pragma unroll
            for (int nt = 0; nt < 4; nt++) {
                uint32_t bo = st + b_off + (uint32_t)(nt * 8 * TSTRIDE * 2 + ks * 32);
                ldsm_x2(bh[nt][0], bh[nt][1], bo + BH);
                ldsm_x2(bl[nt][0], bl[nt][1], bo + BL);
            }
#pragma unroll
            for (int mt = 0; mt < 4; mt++)
#pragma unroll
                for (int nt = 0; nt < 4; nt++) {
                    mma_f16(acc[mt][nt], ah[mt], bh[nt]);   // Xh @ Whi
                    mma_f16(acc[mt][nt], ah[mt], bl[nt]);   // Xh @ Wlo
                }
        }
        __syncthreads();
    }

    const int er = lane >> 2;
    const int ec = (lane & 3) * 2;
#pragma unroll
    for (int mt = 0; mt < 4; mt++) {
#pragma unroll
        for (int nt = 0; nt < 4; nt++) {
            int col = col0 + warp_n * 32 + nt * 8 + ec;
            int r1 = row0 + warp_m * 64 + mt * 16 + er;
            int r2 = r1 + 8;
            float2 v1 = make_float2(acc[mt][nt][0], acc[mt][nt][1]);
            float2 v2 = make_float2(acc[mt][nt][2], acc[mt][nt][3]);
            if (z == 2) {
                v1.x = fmaxf(v1.x, 0.f); v1.y = fmaxf(v1.y, 0.f);
                v2.x = fmaxf(v2.x, 0.f); v2.y = fmaxf(v2.y, 0.f);
                if (r1 < n) *reinterpret_cast<float2*>(g_mlp + (size_t)r1 * FF + col) = v1;
                if (r2 < n) *reinterpret_cast<float2*>(g_mlp + (size_t)r2 * FF + col) = v2;
            } else {
                __half* outh = g_xwh + (size_t)z * NN * FF;
                __half2 h1 = __float22half2_rn(v1);
                __half2 h2 = __float22half2_rn(v2);
                if (r1 < n) *reinterpret_cast<__half2*>(outh + (size_t)r1 * FF + col) = h1;
                if (r2 < n) *reinterpret_cast<__half2*>(outh + (size_t)r2 * FF + col) = h2;
            }
        }
    }
}

// ================= counting sort: histogram =================
__global__ __launch_bounds__(256) void hist_kernel(
    const int* __restrict__ rowA, const int* __restrict__ rowB, int E)
{
    const int m = blockIdx.y;
    const int* __restrict__ row = (m == 0) ? rowA : rowB;
    int* cnt = g_cnt + m * NN;
    int stride = gridDim.x * blockDim.x;
    for (int i = blockIdx.x * blockDim.x + threadIdx.x; i < E; i += stride)
        atomicAdd(&cnt[row[i]], 1);
}

// ================= counting sort: exclusive scan (1 block per matrix) ============
__global__ __launch_bounds__(1024) void scan_kernel(int E) {
    const int m = blockIdx.x;
    const int* cnt = g_cnt + m * NN;
    int* ptr = g_ptr + m * (NN + 1);
    int* off = g_off + m * NN;
    __shared__ int wsum[32];
    __shared__ int carry_s;
    int tid = threadIdx.x;
    int lane = tid & 31, wid = tid >> 5;
    if (tid == 0) carry_s = 0;
    __syncthreads();
    for (int basei = 0; basei < NN; basei += 1024) {
        int i = basei + tid;
        int v = (i < NN) ? cnt[i] : 0;
        int x = v;
#pragma unroll
        for (int o = 1; o < 32; o <<= 1) {
            int y = __shfl_up_sync(0xffffffffu, x, o);
            if (lane >= o) x += y;
        }
        if (lane == 31) wsum[wid] = x;
        __syncthreads();
        if (wid == 0) {
            int s = wsum[lane];
#pragma unroll
            for (int o = 1; o < 32; o <<= 1) {
                int y = __shfl_up_sync(0xffffffffu, s, o);
                if (lane >= o) s += y;
            }
            wsum[lane] = s;
        }
        __syncthreads();
        int incl = x + (wid > 0 ? wsum[wid - 1] : 0);
        int excl = incl - v + carry_s;
        if (i < NN) { ptr[i] = excl; off[i] = excl; }
        __syncthreads();
        if (tid == 1023) carry_s += incl;
        __syncthreads();
    }
    if (threadIdx.x == 0) ptr[NN] = E;
}

// ================= counting sort: scatter packed (val,col) =================
__global__ __launch_bounds__(256) void scatter_kernel(
    const int* __restrict__ rowA, const int* __restrict__ colA, const float* __restrict__ valA,
    const int* __restrict__ rowB, const int* __restrict__ colB, const float* __restrict__ valB,
    int E)
{
    const int m = blockIdx.y;
    const int* __restrict__ row = (m == 0) ? rowA : rowB;
    const int* __restrict__ col = (m == 0) ? colA : colB;
    const float* __restrict__ val = (m == 0) ? valA : valB;
    int* off = g_off + m * NN;
    ull* edges = g_edges + (size_t)m * EMAX;
    int stride = gridDim.x * blockDim.x;
    for (int i = blockIdx.x * blockDim.x + threadIdx.x; i < E; i += stride) {
        int r = row[i];
        int pos = atomicAdd(&off[r], 1);
        ull e = ((ull)__float_as_uint(val[i]) << 32) | (uint32_t)col[i];
        edges[pos] = e;
    }
}

// ================= CSR SpMM: fp16 gather, fp32 result, one warp per row =========
__global__ __launch_bounds__(256) void spmm_csr_kernel(int n)
{
    const int m = blockIdx.y;
    const __half* __restrict__ x = g_xwh + (size_t)m * NN * FF;
    float* __restrict__ acc = (m == 0) ? g_acc0 : g_acc1;
    const ull* __restrict__ edges = g_edges + (size_t)m * EMAX;
    const int* __restrict__ ptr = g_ptr + m * (NN + 1);

    int warp = threadIdx.x >> 5;
    int lane = threadIdx.x & 31;
    int r = blockIdx.x * 8 + warp;
    if (r >= n) return;

    int s = ptr[r], e = ptr[r + 1];
    float a[8];
#pragma unroll
    for (int i = 0; i < 8; i++) a[i] = 0.f;

    for (int b = s; b < e; b += 32) {
        int cntb = min(32, e - b);
        ull my = (b + lane < e) ? __ldg(edges + b + lane) : 0ull;
        for (int j = 0; j < cntb; j++) {
            ull ed = __shfl_sync(0xffffffffu, my, j);
            int c = (int)(uint32_t)ed;
            float v = __uint_as_float((uint32_t)(ed >> 32));
            uint4 h = __ldg(reinterpret_cast<const uint4*>(x + (size_t)c * FF) + lane);
            float2 f0 = __half22float2(*reinterpret_cast<__half2*>(&h.x));
            float2 f1 = __half22float2(*reinterpret_cast<__half2*>(&h.y));
            float2 f2 = __half22float2(*reinterpret_cast<__half2*>(&h.z));
            float2 f3 = __half22float2(*reinterpret_cast<__half2*>(&h.w));
            a[0] = fmaf(v, f0.x, a[0]); a[1] = fmaf(v, f0.y, a[1]);
            a[2] = fmaf(v, f1.x, a[2]); a[3] = fmaf(v, f1.y, a[3]);
            a[4] = fmaf(v, f2.x, a[4]); a[5] = fmaf(v, f2.y, a[5]);
            a[6] = fmaf(v, f3.x, a[6]); a[7] = fmaf(v, f3.y, a[7]);
        }
    }
    float* dst = acc + (size_t)r * FF + lane * 8;
    *reinterpret_cast<float4*>(dst) = make_float4(a[0], a[1], a[2], a[3]);
    *reinterpret_cast<float4*>(dst + 4) = make_float4(a[4], a[5], a[6], a[7]);
}

// ================= column sums (vectorized float4) =================
__global__ __launch_bounds__(256) void colsum_kernel(int n) {
    int c4 = threadIdx.x & 63;
    int rl = threadIdx.x >> 6;
    float4 s0 = make_float4(0.f, 0.f, 0.f, 0.f);
    float4 s1 = s0, s2 = s0;
    for (int r = blockIdx.x * 4 + rl; r < n; r += gridDim.x * 4) {
        size_t o = (size_t)r * (FF / 4) + c4;
        float4 a = reinterpret_cast<const float4*>(g_acc0)[o];
        float4 b = reinterpret_cast<const float4*>(g_acc1)[o];
        float4 mm = reinterpret_cast<const float4*>(g_mlp)[o];
        s0.x += fmaxf(a.x, 0.f); s0.y += fmaxf(a.y, 0.f); s0.z += fmaxf(a.z, 0.f); s0.w += fmaxf(a.w, 0.f);
        s1.x += fmaxf(b.x, 0.f); s1.y += fmaxf(b.y, 0.f); s1.z += fmaxf(b.z, 0.f); s1.w += fmaxf(b.w, 0.f);
        s2.x += mm.x; s2.y += mm.y; s2.z += mm.z; s2.w += mm.w;
    }
    red_add_v4(&g_colsum[c4 * 4], s0);
    red_add_v4(&g_colsum[FF + c4 * 4], s1);
    red_add_v4(&g_colsum[2 * FF + c4 * 4], s2);
}

// ================= tiny attention precompute =================
__global__ __launch_bounds__(256) void attn_small_kernel(
    const float* __restrict__ Wk0, const float* __restrict__ Wk1, const float* __restrict__ Wk2,
    const float* __restrict__ avA, const float* __restrict__ avA2, const float* __restrict__ avM,
    int n)
{
    __shared__ float m[3][FF];
    __shared__ float kk[3][64];
    int tid = threadIdx.x;
    float invn = 1.0f / (float)n;
    m[0][tid] = g_colsum[tid] * invn;
    m[1][tid] = g_colsum[FF + tid] * invn;
    m[2][tid] = g_colsum[2 * FF + tid] * invn;
    __syncthreads();
    int j = tid >> 6;
    int h = tid & 63;
    if (j < 3) {
        const float* Wk = (j == 0) ? Wk0 : ((j == 1) ? Wk1 : Wk2);
        float s = 0.f;
#pragma unroll 8
        for (int c = 0; c < FF; c++) s += m[j][c] * Wk[c * 64 + h];
        kk[j][h] = s;
    }
    __syncthreads();
#pragma unroll
    for (int jj = 0; jj < 3; jj++) {
        const float* av = (jj == 0) ? avA : ((jj == 1) ? avA2 : avM);
        float s = 0.f;
#pragma unroll 8
        for (int hh = 0; hh < 64; hh++) s += av[tid * 64 + hh] * kk[jj][hh];
        g_v[jj * FF + tid] = s;
    }
}

// ================= final: gates + weighted combine =================
__global__ __launch_bounds__(256) void final_kernel(
    const float* __restrict__ attvec, float* __restrict__ out, int n)
{
    __shared__ float sv[3 * FF];
    __shared__ float sav[9];
    int tid = threadIdx.x;
    for (int i = tid; i < 3 * FF; i += 256) sv[i] = g_v[i];
    if (tid < 9) sav[tid] = attvec[tid];
    __syncthreads();

    int warp = tid >> 5;
    int lane = tid & 31;
    int node = blockIdx.x * 8 + warp;
    if (node >= n) return;

    size_t base = (size_t)node * FF;
    const float4* pa = reinterpret_cast<const float4*>(g_acc0 + base);
    const float4* pb = reinterpret_cast<const float4*>(g_acc1 + base);
    const float4* pm = reinterpret_cast<const float4*>(g_mlp + base);

    float4 a0 = pa[lane], a1 = pa[lane + 32];
    float4 b0 = pb[lane], b1 = pb[lane + 32];
    float4 m0 = pm[lane], m1 = pm[lane + 32];
    a0.x = fmaxf(a0.x, 0.f); a0.y = fmaxf(a0.y, 0.f); a0.z = fmaxf(a0.z, 0.f); a0.w = fmaxf(a0.w, 0.f);
    a1.x = fmaxf(a1.x, 0.f); a1.y = fmaxf(a1.y, 0.f); a1.z = fmaxf(a1.z, 0.f); a1.w = fmaxf(a1.w, 0.f);
    b0.x = fmaxf(b0.x, 0.f); b0.y = fmaxf(b0.y, 0.f); b0.z = fmaxf(b0.z, 0.f); b0.w = fmaxf(b0.w, 0.f);
    b1.x = fmaxf(b1.x, 0.f); b1.y = fmaxf(b1.y, 0.f); b1.z = fmaxf(b1.z, 0.f); b1.w = fmaxf(b1.w, 0.f);

    const float4* v0p = reinterpret_cast<const float4*>(sv);
    const float4* v1p = reinterpret_cast<const float4*>(sv + FF);
    const float4* v2p = reinterpret_cast<const float4*>(sv + 2 * FF);
    float4 v00 = v0p[lane], v01 = v0p[lane + 32];
    float4 v10 = v1p[lane], v11 = v1p[lane + 32];
    float4 v20 = v2p[lane], v21 = v2p[lane + 32];

    float d0 = a0.x * v00.x + a0.y * v00.y + a0.z * v00.z + a0.w * v00.w
             + a1.x * v01.x + a1.y * v01.y + a1.z * v01.z + a1.w * v01.w;
    float d1 = b0.x * v10.x + b0.y * v10.y + b0.z * v10.z + b0.w * v10.w
             + b1.x * v11.x + b1.y * v11.y + b1.z * v11.z + b1.w * v11.w;
    float d2 = m0.x * v20.x + m0.y * v20.y + m0.z * v20.z + m0.w * v20.w
             + m1.x * v21.x + m1.y * v21.y + m1.z * v21.z + m1.w * v21.w;

#pragma unroll
    for (int o = 16; o > 0; o >>= 1) {
        d0 += __shfl_xor_sync(0xffffffffu, d0, o);
        d1 += __shfl_xor_sync(0xffffffffu, d1, o);
        d2 += __shfl_xor_sync(0xffffffffu, d2, o);
    }

    float s0 = 1.f / (1.f + __expf(-d0));
    float s1 = 1.f / (1.f + __expf(-d1));
    float s2 = 1.f / (1.f + __expf(-d2));
    float zz[3];
#pragma unroll
    for (int i = 0; i < 3; i++)
        zz[i] = (s0 * sav[0 * 3 + i] + s1 * sav[1 * 3 + i] + s2 * sav[2 * 3 + i]) * (1.0f / 3.0f);
    float mx = fmaxf(zz[0], fmaxf(zz[1], zz[2]));
    float e0 = __expf(zz[0] - mx), e1 = __expf(zz[1] - mx), e2 = __expf(zz[2] - mx);
    float inv = 1.f / (e0 + e1 + e2);
    float g0 = 3.f * e0 * inv, g1 = 3.f * e1 * inv, g2 = 3.f * e2 * inv;

    float4 o0, o1;
    o0.x = g0 * a0.x + g1 * b0.x + g2 * m0.x;
    o0.y = g0 * a0.y + g1 * b0.y + g2 * m0.y;
    o0.z = g0 * a0.z + g1 * b0.z + g2 * m0.z;
    o0.w = g0 * a0.w + g1 * b0.w + g2 * m0.w;
    o1.x = g0 * a1.x + g1 * b1.x + g2 * m1.x;
    o1.y = g0 * a1.y + g1 * b1.y + g2 * m1.y;
    o1.z = g0 * a1.z + g1 * b1.z + g2 * m1.z;
    o1.w = g0 * a1.w + g1 * b1.w + g2 * m1.w;

    float4* po = reinterpret_cast<float4*>(out + base);
    po[lane] = o0;
    po[lane + 32] = o1;
}

// ================= launch =================
extern "C" void kernel_launch(void* const* d_in, const int* in_sizes, int n_in,
                              void* d_out, int out_size)
{
    const float* inputx = (const float*)d_in[0];
    const int* row_A = (const int*)d_in[1];
    const int* col_A = (const int*)d_in[2];
    const float* val_A = (const float*)d_in[3];
    const int* row_A2 = (const int*)d_in[4];
    const int* col_A2 = (const int*)d_in[5];
    const float* val_A2 = (const float*)d_in[6];
    const float* weight_A = (const float*)d_in[7];
    const float* weight_A2 = (const float*)d_in[8];
    const float* weight_mlp = (const float*)d_in[9];
    const float* W_k0 = (const float*)d_in[10];
    const float* W_k1 = (const float*)d_in[11];
    const float* W_k2 = (const float*)d_in[12];
    const float* att_vec_A = (const float*)d_in[13];
    const float* att_vec_A2 = (const float*)d_in[14];
    const float* att_vec_mlp = (const float*)d_in[15];
    const float* att_vec = (const float*)d_in[16];
    float* out = (float*)d_out;

    const int n = in_sizes[0] / FF;
    const int E = in_sizes[1];

    // One-time setup on the (non-captured) correctness call.
    static cudaStream_t s2 = nullptr;
    static cudaEvent_t ev_fork = nullptr, ev_join = nullptr;
    static bool configured = false;
    if (!configured) {
        cudaFuncSetAttribute(gemm_mma_kernel, cudaFuncAttributeMaxDynamicSharedMemorySize,
                             GEMM_SMEM_BYTES);
        cudaStreamCreateWithFlags(&s2, cudaStreamNonBlocking);
        cudaEventCreateWithFlags(&ev_fork, cudaEventDisableTiming);
        cudaEventCreateWithFlags(&ev_join, cudaEventDisableTiming);
        configured = true;
    }

    // 0) zero small scratch
    zero_small_kernel<<<(2 * NN + 255) / 256, 256>>>();
    cudaEventRecord(ev_fork, 0);
    cudaStreamWaitEvent(s2, ev_fork, 0);

    // --- stream s2: counting sort of both edge lists by row ---
    {
        dim3 grid(1184, 2);
        hist_kernel<<<grid, 256, 0, s2>>>(row_A, row_A2, E);
        scan_kernel<<<2, 1024, 0, s2>>>(E);
        scatter_kernel<<<grid, 256, 0, s2>>>(row_A, col_A, val_A, row_A2, col_A2, val_A2, E);
    }
    cudaEventRecord(ev_join, s2);

    // --- default stream: converts + GEMM (3 weights, one launch) ---
    convert_x_kernel<<<148 * 20, 256>>>(inputx, n);
    {
        dim3 grid(FF * FF / 256, 3);
        convert_w_kernel<<<grid, 256>>>(weight_A, weight_A2, weight_mlp);
    }
    {
        dim3 grid((n + 127) / 128, FF / 128, 3);
        gemm_mma_kernel<<<grid, 256, GEMM_SMEM_BYTES>>>(n);
    }

    // join: SpMM needs both GEMM output and sorted edges
    cudaStreamWaitEvent(0, ev_join, 0);

    // 4) CSR SpMM: fp16 gather, both matrices concurrent (102MB L2-resident)
    {
        dim3 grid((n + 7) / 8, 2);
        spmm_csr_kernel<<<grid, 256>>>(n);
    }

    // 5) column means (vectorized)
    colsum_kernel<<<1184, 256>>>(n);

    // 6) gate vectors
    attn_small_kernel<<<1, 256>>>(W_k0, W_k1, W_k2, att_vec_A, att_vec_A2, att_vec_mlp, n);

    // 7) fused gating + combine
    final_kernel<<<(n + 7) / 8, 256>>>(att_vec, out, n);
}

// round 16
// speedup vs baseline: 1.3068x; 1.0986x over previous
#include <cuda_runtime.h>
#include <cuda_fp16.h>
#include <cstdint>
#include <cstdio>

#define NN 100000
#define FF 256
#define EMAX 3200000

typedef unsigned long long ull;

// ================= scratch (device globals; no allocation allowed) =================
__device__ __align__(256) __half g_xwh[2 * (size_t)NN * FF];  // X@W_A, X@W_A2 fp16 (SpMM gather)
__device__ float g_mlp[(size_t)NN * FF];       // relu(X @ W_mlp) fp32
__device__ float g_acc0[(size_t)NN * FF];      // spmm result A
__device__ float g_acc1[(size_t)NN * FF];      // spmm result A2
__device__ float g_colsum[3 * FF];
__device__ float g_v[3 * FF];
__device__ __align__(256) __half g_xh[(size_t)NN * FF];   // fp16(X)
__device__ __align__(256) __half g_wth[3 * FF * FF];      // fp16(W^T)
// counting-sort scratch
__device__ int g_cnt[2 * NN];
__device__ int g_ptr[2 * (NN + 1)];
__device__ int g_off[2 * NN];
__device__ __align__(256) ull g_edges[2 * (size_t)EMAX];  // packed (val<<32 | col), row-sorted

// ================= helpers =================
__device__ __forceinline__ uint32_t smem_u32(const void* p) {
    uint32_t a;
    asm("{ .reg .u64 t; cvta.to.shared.u64 t, %1; cvt.u32.u64 %0, t; }" : "=r"(a) : "l"(p));
    return a;
}
__device__ __forceinline__ void cp_async16(uint32_t dst, const void* src, uint32_t bytes) {
    asm volatile("cp.async.ca.shared.global [%0], [%1], 16, %2;"
                 :: "r"(dst), "l"(src), "r"(bytes) : "memory");
}
#define CP_COMMIT() asm volatile("cp.async.commit_group;" ::: "memory")
#define CP_WAIT0()  asm volatile("cp.async.wait_group 0;" ::: "memory")
#define CP_WAIT1()  asm volatile("cp.async.wait_group 1;" ::: "memory")

__device__ __forceinline__ void ldsm_x4(uint32_t& r0, uint32_t& r1, uint32_t& r2, uint32_t& r3,
                                        uint32_t addr) {
    asm volatile("ldmatrix.sync.aligned.m8n8.x4.shared.b16 {%0,%1,%2,%3}, [%4];"
                 : "=r"(r0), "=r"(r1), "=r"(r2), "=r"(r3) : "r"(addr));
}
__device__ __forceinline__ void ldsm_x2(uint32_t& r0, uint32_t& r1, uint32_t addr) {
    asm volatile("ldmatrix.sync.aligned.m8n8.x2.shared.b16 {%0,%1}, [%2];"
                 : "=r"(r0), "=r"(r1) : "r"(addr));
}
__device__ __forceinline__ void mma_f16(float* d, const uint32_t* a, const uint32_t* b) {
    asm volatile(
        "mma.sync.aligned.m16n8k16.row.col.f32.f16.f16.f32 "
        "{%0,%1,%2,%3}, {%4,%5,%6,%7}, {%8,%9}, {%0,%1,%2,%3};"
        : "+f"(d[0]), "+f"(d[1]), "+f"(d[2]), "+f"(d[3])
        : "r"(a[0]), "r"(a[1]), "r"(a[2]), "r"(a[3]), "r"(b[0]), "r"(b[1]));
}
__device__ __forceinline__ void red_add_v4(float* p, float4 v) {
    asm volatile("red.relaxed.gpu.global.add.v4.f32 [%0], {%1,%2,%3,%4};"
                 :: "l"(p), "f"(v.x), "f"(v.y), "f"(v.z), "f"(v.w) : "memory");
}

// ================= zero histograms + colsum =================
__global__ void zero_small_kernel() {
    int t = blockIdx.x * blockDim.x + threadIdx.x;
    if (t < 2 * NN) g_cnt[t] = 0;
    if (t < 3 * FF) g_colsum[t] = 0.f;
}

// ================= convert X -> fp16 =================
__global__ __launch_bounds__(256) void convert_x_kernel(const float* __restrict__ X, int n) {
    size_t total4 = (size_t)n * (FF / 4);
    size_t stride = (size_t)gridDim.x * blockDim.x;
    for (size_t i4 = (size_t)blockIdx.x * blockDim.x + threadIdx.x; i4 < total4; i4 += stride) {
        float4 x = reinterpret_cast<const float4*>(X)[i4];
        __half2 h0 = __float22half2_rn(make_float2(x.x, x.y));
        __half2 h1 = __float22half2_rn(make_float2(x.z, x.w));
        size_t i = i4 * 4;
        reinterpret_cast<__half2*>(g_xh + i)[0] = h0;
        reinterpret_cast<__half2*>(g_xh + i)[1] = h1;
    }
}

// ================= transpose + convert W -> fp16 =================
__global__ __launch_bounds__(256) void convert_w_kernel(
    const float* __restrict__ W0, const float* __restrict__ W1, const float* __restrict__ W2)
{
    int z = blockIdx.y;
    const float* W = (z == 0) ? W0 : ((z == 1) ? W1 : W2);
    int t = blockIdx.x * 256 + threadIdx.x;
    int k = t & 255;
    int nn = t >> 8;
    g_wth[(size_t)z * 65536 + nn * 256 + k] = __float2half_rn(W[k * 256 + nn]);
}

// ================= HMMA GEMM (plain fp16): z<2 -> fp16 xw, z==2 -> relu fp32 mlp
// __launch_bounds__(256,2): 2 CTAs/SM hide sync/epilogue tensor-idle gaps.
static constexpr int TSTRIDE = 40;
static constexpr int TILE_B = 128 * TSTRIDE * 2;
static constexpr int STAGE_B = 2 * TILE_B;          // A, B
static constexpr uint32_t GEMM_SMEM_BYTES = 2 * STAGE_B + 256;

__global__ __launch_bounds__(256, 2) void gemm_mma_kernel(int n)
{
    extern __shared__ char dynsmem[];
    uint32_t raw = smem_u32(dynsmem);
    uint32_t base = (raw + 127) & ~127u;

    const int z = blockIdx.z;
    const __half* __restrict__ WH = g_wth + (size_t)z * 65536;

    const int row0 = blockIdx.x * 128;
    const int col0 = blockIdx.y * 128;
    const int tid = threadIdx.x;
    const int wid = tid >> 5;
    const int lane = tid & 31;
    const int warp_m = wid & 1;
    const int warp_n = wid >> 1;

    const uint32_t AT = 0, BT = TILE_B;

    auto load_chunk = [&](int s, int c) {
        const uint32_t st = base + s * STAGE_B;
        const int k0 = c * 32;
#pragma unroll
        for (int it = 0; it < 2; it++) {
            int idx = tid + it * 256;
            int r = idx >> 2;
            int q = idx & 3;
            uint32_t dsto = (uint32_t)(r * (TSTRIDE * 2) + q * 16);
            int gr = row0 + r;
            uint32_t sz = (gr < n) ? 16u : 0u;
            const __half* sa = g_xh + (size_t)(gr < n ? gr : 0) * FF + k0 + q * 8;
            cp_async16(st + AT + dsto, sa, sz);
            int nr = col0 + r;
            cp_async16(st + BT + dsto, WH + (size_t)nr * FF + k0 + q * 8, 16);
        }
        CP_COMMIT();
    };

    float acc[4][4][4];
#pragma unroll
    for (int i = 0; i < 4; i++)
#pragma unroll
        for (int j = 0; j < 4; j++)
#pragma unroll
            for (int q = 0; q < 4; q++) acc[i][j][q] = 0.f;

    const uint32_t a_off = (uint32_t)((warp_m * 64 + (lane & 15)) * (TSTRIDE * 2) + (lane >> 4) * 16);
    const uint32_t b_off = (uint32_t)((warp_n * 32 + (lane & 7)) * (TSTRIDE * 2) + ((lane >> 3) & 1) * 16);

    load_chunk(0, 0);

    for (int c = 0; c < 8; c++) {
        const int s = c & 1;
        if (c < 7) load_chunk(s ^ 1, c + 1);
        if (c < 7) { CP_WAIT1(); } else { CP_WAIT0(); }
        __syncthreads();

        const uint32_t st = base + s * STAGE_B;
#pragma unroll
        for (int ks = 0; ks < 2; ks++) {
            uint32_t ah[4][4], bt[4][2];
#pragma unroll
            for (int mt = 0; mt < 4; mt++) {
                uint32_t ao = st + a_off + (uint32_t)(mt * 16 * TSTRIDE * 2 + ks * 32);
                ldsm_x4(ah[mt][0], ah[mt][1], ah[mt][2], ah[mt][3], ao + AT);
            }
#pragma unroll
            for (int nt = 0; nt < 4; nt++) {
                uint32_t bo = st + b_off + (uint32_t)(nt * 8 * TSTRIDE * 2 + ks * 32);
                ldsm_x2(bt[nt][0], bt[nt][1], bo + BT);
            }
#pragma unroll
            for (int mt = 0; mt < 4; mt++)
#pragma unroll
                for (int nt = 0; nt < 4; nt++)
                    mma_f16(acc[mt][nt], ah[mt], bt[nt]);
        }
        __syncthreads();
    }

    const int er = lane >> 2;
    const int ec = (lane & 3) * 2;
#pragma unroll
    for (int mt = 0; mt < 4; mt++) {
#pragma unroll
        for (int nt = 0; nt < 4; nt++) {
            int col = col0 + warp_n * 32 + nt * 8 + ec;
            int r1 = row0 + warp_m * 64 + mt * 16 + er;
            int r2 = r1 + 8;
            float2 v1 = make_float2(acc[mt][nt][0], acc[mt][nt][1]);
            float2 v2 = make_float2(acc[mt][nt][2], acc[mt][nt][3]);
            if (z == 2) {
                v1.x = fmaxf(v1.x, 0.f); v1.y = fmaxf(v1.y, 0.f);
                v2.x = fmaxf(v2.x, 0.f); v2.y = fmaxf(v2.y, 0.f);
                if (r1 < n) *reinterpret_cast<float2*>(g_mlp + (size_t)r1 * FF + col) = v1;
                if (r2 < n) *reinterpret_cast<float2*>(g_mlp + (size_t)r2 * FF + col) = v2;
            } else {
                __half* outh = g_xwh + (size_t)z * NN * FF;
                __half2 h1 = __float22half2_rn(v1);
                __half2 h2 = __float22half2_rn(v2);
                if (r1 < n) *reinterpret_cast<__half2*>(outh + (size_t)r1 * FF + col) = h1;
                if (r2 < n) *reinterpret_cast<__half2*>(outh + (size_t)r2 * FF + col) = h2;
            }
        }
    }
}

// ================= counting sort: histogram =================
__global__ __launch_bounds__(256) void hist_kernel(
    const int* __restrict__ rowA, const int* __restrict__ rowB, int E)
{
    const int m = blockIdx.y;
    const int* __restrict__ row = (m == 0) ? rowA : rowB;
    int* cnt = g_cnt + m * NN;
    int stride = gridDim.x * blockDim.x;
    for (int i = blockIdx.x * blockDim.x + threadIdx.x; i < E; i += stride)
        atomicAdd(&cnt[row[i]], 1);
}

// ================= counting sort: exclusive scan (1 block per matrix) ============
__global__ __launch_bounds__(1024) void scan_kernel(int E) {
    const int m = blockIdx.x;
    const int* cnt = g_cnt + m * NN;
    int* ptr = g_ptr + m * (NN + 1);
    int* off = g_off + m * NN;
    __shared__ int wsum[32];
    __shared__ int carry_s;
    int tid = threadIdx.x;
    int lane = tid & 31, wid = tid >> 5;
    if (tid == 0) carry_s = 0;
    __syncthreads();
    for (int basei = 0; basei < NN; basei += 1024) {
        int i = basei + tid;
        int v = (i < NN) ? cnt[i] : 0;
        int x = v;
#pragma unroll
        for (int o = 1; o < 32; o <<= 1) {
            int y = __shfl_up_sync(0xffffffffu, x, o);
            if (lane >= o) x += y;
        }
        if (lane == 31) wsum[wid] = x;
        __syncthreads();
        if (wid == 0) {
            int s = wsum[lane];
#pragma unroll
            for (int o = 1; o < 32; o <<= 1) {
                int y = __shfl_up_sync(0xffffffffu, s, o);
                if (lane >= o) s += y;
            }
            wsum[lane] = s;
        }
        __syncthreads();
        int incl = x + (wid > 0 ? wsum[wid - 1] : 0);
        int excl = incl - v + carry_s;
        if (i < NN) { ptr[i] = excl; off[i] = excl; }
        __syncthreads();
        if (tid == 1023) carry_s += incl;
        __syncthreads();
    }
    if (threadIdx.x == 0) ptr[NN] = E;
}

// ================= counting sort: scatter packed (val,col) =================
__global__ __launch_bounds__(256) void scatter_kernel(
    const int* __restrict__ rowA, const int* __restrict__ colA, const float* __restrict__ valA,
    const int* __restrict__ rowB, const int* __restrict__ colB, const float* __restrict__ valB,
    int E)
{
    const int m = blockIdx.y;
    const int* __restrict__ row = (m == 0) ? rowA : rowB;
    const int* __restrict__ col = (m == 0) ? colA : colB;
    const float* __restrict__ val = (m == 0) ? valA : valB;
    int* off = g_off + m * NN;
    ull* edges = g_edges + (size_t)m * EMAX;
    int stride = gridDim.x * blockDim.x;
    for (int i = blockIdx.x * blockDim.x + threadIdx.x; i < E; i += stride) {
        int r = row[i];
        int pos = atomicAdd(&off[r], 1);
        ull e = ((ull)__float_as_uint(val[i]) << 32) | (uint32_t)col[i];
        edges[pos] = e;
    }
}

// ================= CSR SpMM: fp16 gather, fp32 result, one warp per row =========
__global__ __launch_bounds__(256) void spmm_csr_kernel(int n)
{
    const int m = blockIdx.y;
    const __half* __restrict__ x = g_xwh + (size_t)m * NN * FF;
    float* __restrict__ acc = (m == 0) ? g_acc0 : g_acc1;
    const ull* __restrict__ edges = g_edges + (size_t)m * EMAX;
    const int* __restrict__ ptr = g_ptr + m * (NN + 1);

    int warp = threadIdx.x >> 5;
    int lane = threadIdx.x & 31;
    int r = blockIdx.x * 8 + warp;
    if (r >= n) return;

    int s = ptr[r], e = ptr[r + 1];
    float a[8];
#pragma unroll
    for (int i = 0; i < 8; i++) a[i] = 0.f;

    for (int b = s; b < e; b += 32) {
        int cntb = min(32, e - b);
        ull my = (b + lane < e) ? __ldg(edges + b + lane) : 0ull;
        for (int j = 0; j < cntb; j++) {
            ull ed = __shfl_sync(0xffffffffu, my, j);
            int c = (int)(uint32_t)ed;
            float v = __uint_as_float((uint32_t)(ed >> 32));
            uint4 h = __ldg(reinterpret_cast<const uint4*>(x + (size_t)c * FF) + lane);
            float2 f0 = __half22float2(*reinterpret_cast<__half2*>(&h.x));
            float2 f1 = __half22float2(*reinterpret_cast<__half2*>(&h.y));
            float2 f2 = __half22float2(*reinterpret_cast<__half2*>(&h.z));
            float2 f3 = __half22float2(*reinterpret_cast<__half2*>(&h.w));
            a[0] = fmaf(v, f0.x, a[0]); a[1] = fmaf(v, f0.y, a[1]);
            a[2] = fmaf(v, f1.x, a[2]); a[3] = fmaf(v, f1.y, a[3]);
            a[4] = fmaf(v, f2.x, a[4]); a[5] = fmaf(v, f2.y, a[5]);
            a[6] = fmaf(v, f3.x, a[6]); a[7] = fmaf(v, f3.y, a[7]);
        }
    }
    float* dst = acc + (size_t)r * FF + lane * 8;
    *reinterpret_cast<float4*>(dst) = make_float4(a[0], a[1], a[2], a[3]);
    *reinterpret_cast<float4*>(dst + 4) = make_float4(a[4], a[5], a[6], a[7]);
}

// ================= column sums (vectorized float4) =================
__global__ __launch_bounds__(256) void colsum_kernel(int n) {
    int c4 = threadIdx.x & 63;
    int rl = threadIdx.x >> 6;
    float4 s0 = make_float4(0.f, 0.f, 0.f, 0.f);
    float4 s1 = s0, s2 = s0;
    for (int r = blockIdx.x * 4 + rl; r < n; r += gridDim.x * 4) {
        size_t o = (size_t)r * (FF / 4) + c4;
        float4 a = reinterpret_cast<const float4*>(g_acc0)[o];
        float4 b = reinterpret_cast<const float4*>(g_acc1)[o];
        float4 mm = reinterpret_cast<const float4*>(g_mlp)[o];
        s0.x += fmaxf(a.x, 0.f); s0.y += fmaxf(a.y, 0.f); s0.z += fmaxf(a.z, 0.f); s0.w += fmaxf(a.w, 0.f);
        s1.x += fmaxf(b.x, 0.f); s1.y += fmaxf(b.y, 0.f); s1.z += fmaxf(b.z, 0.f); s1.w += fmaxf(b.w, 0.f);
        s2.x += mm.x; s2.y += mm.y; s2.z += mm.z; s2.w += mm.w;
    }
    red_add_v4(&g_colsum[c4 * 4], s0);
    red_add_v4(&g_colsum[FF + c4 * 4], s1);
    red_add_v4(&g_colsum[2 * FF + c4 * 4], s2);
}

// ================= tiny attention precompute =================
__global__ __launch_bounds__(256) void attn_small_kernel(
    const float* __restrict__ Wk0, const float* __restrict__ Wk1, const float* __restrict__ Wk2,
    const float* __restrict__ avA, const float* __restrict__ avA2, const float* __restrict__ avM,
    int n)
{
    __shared__ float m[3][FF];
    __shared__ float kk[3][64];
    int tid = threadIdx.x;
    float invn = 1.0f / (float)n;
    m[0][tid] = g_colsum[tid] * invn;
    m[1][tid] = g_colsum[FF + tid] * invn;
    m[2][tid] = g_colsum[2 * FF + tid] * invn;
    __syncthreads();
    int j = tid >> 6;
    int h = tid & 63;
    if (j < 3) {
        const float* Wk = (j == 0) ? Wk0 : ((j == 1) ? Wk1 : Wk2);
        float s = 0.f;
#pragma unroll 8
        for (int c = 0; c < FF; c++) s += m[j][c] * Wk[c * 64 + h];
        kk[j][h] = s;
    }
    __syncthreads();
#pragma unroll
    for (int jj = 0; jj < 3; jj++) {
        const float* av = (jj == 0) ? avA : ((jj == 1) ? avA2 : avM);
        float s = 0.f;
#pragma unroll 8
        for (int hh = 0; hh < 64; hh++) s += av[tid * 64 + hh] * kk[jj][hh];
        g_v[jj * FF + tid] = s;
    }
}

// ================= final: gates + weighted combine =================
__global__ __launch_bounds__(256) void final_kernel(
    const float* __restrict__ attvec, float* __restrict__ out, int n)
{
    __shared__ float sv[3 * FF];
    __shared__ float sav[9];
    int tid = threadIdx.x;
    for (int i = tid; i < 3 * FF; i += 256) sv[i] = g_v[i];
    if (tid < 9) sav[tid] = attvec[tid];
    __syncthreads();

    int warp = tid >> 5;
    int lane = tid & 31;
    int node = blockIdx.x * 8 + warp;
    if (node >= n) return;

    size_t base = (size_t)node * FF;
    const float4* pa = reinterpret_cast<const float4*>(g_acc0 + base);
    const float4* pb = reinterpret_cast<const float4*>(g_acc1 + base);
    const float4* pm = reinterpret_cast<const float4*>(g_mlp + base);

    float4 a0 = pa[lane], a1 = pa[lane + 32];
    float4 b0 = pb[lane], b1 = pb[lane + 32];
    float4 m0 = pm[lane], m1 = pm[lane + 32];
    a0.x = fmaxf(a0.x, 0.f); a0.y = fmaxf(a0.y, 0.f); a0.z = fmaxf(a0.z, 0.f); a0.w = fmaxf(a0.w, 0.f);
    a1.x = fmaxf(a1.x, 0.f); a1.y = fmaxf(a1.y, 0.f); a1.z = fmaxf(a1.z, 0.f); a1.w = fmaxf(a1.w, 0.f);
    b0.x = fmaxf(b0.x, 0.f); b0.y = fmaxf(b0.y, 0.f); b0.z = fmaxf(b0.z, 0.f); b0.w = fmaxf(b0.w, 0.f);
    b1.x = fmaxf(b1.x, 0.f); b1.y = fmaxf(b1.y, 0.f); b1.z = fmaxf(b1.z, 0.f); b1.w = fmaxf(b1.w, 0.f);

    const float4* v0p = reinterpret_cast<const float4*>(sv);
    const float4* v1p = reinterpret_cast<const float4*>(sv + FF);
    const float4* v2p = reinterpret_cast<const float4*>(sv + 2 * FF);
    float4 v00 = v0p[lane], v01 = v0p[lane + 32];
    float4 v10 = v1p[lane], v11 = v1p[lane + 32];
    float4 v20 = v2p[lane], v21 = v2p[lane + 32];

    float d0 = a0.x * v00.x + a0.y * v00.y + a0.z * v00.z + a0.w * v00.w
             + a1.x * v01.x + a1.y * v01.y + a1.z * v01.z + a1.w * v01.w;
    float d1 = b0.x * v10.x + b0.y * v10.y + b0.z * v10.z + b0.w * v10.w
             + b1.x * v11.x + b1.y * v11.y + b1.z * v11.z + b1.w * v11.w;
    float d2 = m0.x * v20.x + m0.y * v20.y + m0.z * v20.z + m0.w * v20.w
             + m1.x * v21.x + m1.y * v21.y + m1.z * v21.z + m1.w * v21.w;

#pragma unroll
    for (int o = 16; o > 0; o >>= 1) {
        d0 += __shfl_xor_sync(0xffffffffu, d0, o);
        d1 += __shfl_xor_sync(0xffffffffu, d1, o);
        d2 += __shfl_xor_sync(0xffffffffu, d2, o);
    }

    float s0 = 1.f / (1.f + __expf(-d0));
    float s1 = 1.f / (1.f + __expf(-d1));
    float s2 = 1.f / (1.f + __expf(-d2));
    float zz[3];
#pragma unroll
    for (int i = 0; i < 3; i++)
        zz[i] = (s0 * sav[0 * 3 + i] + s1 * sav[1 * 3 + i] + s2 * sav[2 * 3 + i]) * (1.0f / 3.0f);
    float mx = fmaxf(zz[0], fmaxf(zz[1], zz[2]));
    float e0 = __expf(zz[0] - mx), e1 = __expf(zz[1] - mx), e2 = __expf(zz[2] - mx);
    float inv = 1.f / (e0 + e1 + e2);
    float g0 = 3.f * e0 * inv, g1 = 3.f * e1 * inv, g2 = 3.f * e2 * inv;

    float4 o0, o1;
    o0.x = g0 * a0.x + g1 * b0.x + g2 * m0.x;
    o0.y = g0 * a0.y + g1 * b0.y + g2 * m0.y;
    o0.z = g0 * a0.z + g1 * b0.z + g2 * m0.z;
    o0.w = g0 * a0.w + g1 * b0.w + g2 * m0.w;
    o1.x = g0 * a1.x + g1 * b1.x + g2 * m1.x;
    o1.y = g0 * a1.y + g1 * b1.y + g2 * m1.y;
    o1.z = g0 * a1.z + g1 * b1.z + g2 * m1.z;
    o1.w = g0 * a1.w + g1 * b1.w + g2 * m1.w;

    float4* po = reinterpret_cast<float4*>(out + base);
    po[lane] = o0;
    po[lane + 32] = o1;
}

// ================= launch =================
extern "C" void kernel_launch(void* const* d_in, const int* in_sizes, int n_in,
                              void* d_out, int out_size)
{
    const float* inputx = (const float*)d_in[0];
    const int* row_A = (const int*)d_in[1];
    const int* col_A = (const int*)d_in[2];
    const float* val_A = (const float*)d_in[3];
    const int* row_A2 = (const int*)d_in[4];
    const int* col_A2 = (const int*)d_in[5];
    const float* val_A2 = (const float*)d_in[6];
    const float* weight_A = (const float*)d_in[7];
    const float* weight_A2 = (const float*)d_in[8];
    const float* weight_mlp = (const float*)d_in[9];
    const float* W_k0 = (const float*)d_in[10];
    const float* W_k1 = (const float*)d_in[11];
    const float* W_k2 = (const float*)d_in[12];
    const float* att_vec_A = (const float*)d_in[13];
    const float* att_vec_A2 = (const float*)d_in[14];
    const float* att_vec_mlp = (const float*)d_in[15];
    const float* att_vec = (const float*)d_in[16];
    float* out = (float*)d_out;

    const int n = in_sizes[0] / FF;
    const int E = in_sizes[1];

    // One-time setup on the (non-captured) correctness call.
    static cudaStream_t s2 = nullptr;
    static cudaEvent_t ev_fork = nullptr, ev_join = nullptr;
    static bool configured = false;
    if (!configured) {
        cudaFuncSetAttribute(gemm_mma_kernel, cudaFuncAttributeMaxDynamicSharedMemorySize,
                             GEMM_SMEM_BYTES);
        cudaStreamCreateWithFlags(&s2, cudaStreamNonBlocking);
        cudaEventCreateWithFlags(&ev_fork, cudaEventDisableTiming);
        cudaEventCreateWithFlags(&ev_join, cudaEventDisableTiming);
        configured = true;
    }

    // 0) zero small scratch
    zero_small_kernel<<<(2 * NN + 255) / 256, 256>>>();
    cudaEventRecord(ev_fork, 0);
    cudaStreamWaitEvent(s2, ev_fork, 0);

    // --- stream s2: counting sort of both edge lists by row ---
    {
        dim3 grid(1184, 2);
        hist_kernel<<<grid, 256, 0, s2>>>(row_A, row_A2, E);
        scan_kernel<<<2, 1024, 0, s2>>>(E);
        scatter_kernel<<<grid, 256, 0, s2>>>(row_A, col_A, val_A, row_A2, col_A2, val_A2, E);
    }
    cudaEventRecord(ev_join, s2);

    // --- default stream: converts + GEMM (3 weights, one launch) ---
    convert_x_kernel<<<148 * 20, 256>>>(inputx, n);
    {
        dim3 grid(FF * FF / 256, 3);
        convert_w_kernel<<<grid, 256>>>(weight_A, weight_A2, weight_mlp);
    }
    {
        dim3 grid((n + 127) / 128, FF / 128, 3);
        gemm_mma_kernel<<<grid, 256, GEMM_SMEM_BYTES>>>(n);
    }

    // join: SpMM needs both GEMM output and sorted edges
    cudaStreamWaitEvent(0, ev_join, 0);

    // 4) CSR SpMM: fp16 gather, both matrices concurrent (102MB L2-resident)
    {
        dim3 grid((n + 7) / 8, 2);
        spmm_csr_kernel<<<grid, 256>>>(n);
    }

    // 5) column means (vectorized)
    colsum_kernel<<<1184, 256>>>(n);

    // 6) gate vectors
    attn_small_kernel<<<1, 256>>>(W_k0, W_k1, W_k2, att_vec_A, att_vec_A2, att_vec_mlp, n);

    // 7) fused gating + combine
    final_kernel<<<(n + 7) / 8, 256>>>(att_vec, out, n);
}

// round 17
// speedup vs baseline: 1.3250x; 1.0139x over previous
#include <cuda_runtime.h>
#include <cuda_fp16.h>
#include <cstdint>
#include <cstdio>

#define NN 100000
#define FF 256
#define EMAX 3200000

typedef unsigned long long ull;

// ================= scratch (device globals; no allocation allowed) =================
__device__ __align__(256) __half g_xwh[2 * (size_t)NN * FF];  // X@W_A, X@W_A2 fp16 (SpMM gather)
__device__ float g_mlp[(size_t)NN * FF];       // relu(X @ W_mlp) fp32
__device__ float g_acc0[(size_t)NN * FF];      // spmm result A
__device__ float g_acc1[(size_t)NN * FF];      // spmm result A2
__device__ float g_colsum[3 * FF];
__device__ float g_v[3 * FF];
__device__ __align__(256) __half g_xh[(size_t)NN * FF];   // fp16(X)
__device__ __align__(256) __half g_wth[3 * FF * FF];      // fp16(W^T)
// counting-sort scratch
__device__ int g_cnt[2 * NN];
__device__ int g_ptr[2 * (NN + 1)];
__device__ int g_off[2 * NN];
__device__ __align__(256) ull g_edges[2 * (size_t)EMAX];  // packed (val<<32 | col), row-sorted

// ================= helpers =================
__device__ __forceinline__ uint32_t smem_u32(const void* p) {
    uint32_t a;
    asm("{ .reg .u64 t; cvta.to.shared.u64 t, %1; cvt.u32.u64 %0, t; }" : "=r"(a) : "l"(p));
    return a;
}
__device__ __forceinline__ void cp_async16(uint32_t dst, const void* src, uint32_t bytes) {
    asm volatile("cp.async.ca.shared.global [%0], [%1], 16, %2;"
                 :: "r"(dst), "l"(src), "r"(bytes) : "memory");
}
#define CP_COMMIT() asm volatile("cp.async.commit_group;" ::: "memory")
#define CP_WAIT0()  asm volatile("cp.async.wait_group 0;" ::: "memory")
#define CP_WAIT1()  asm volatile("cp.async.wait_group 1;" ::: "memory")

__device__ __forceinline__ void ldsm_x4(uint32_t& r0, uint32_t& r1, uint32_t& r2, uint32_t& r3,
                                        uint32_t addr) {
    asm volatile("ldmatrix.sync.aligned.m8n8.x4.shared.b16 {%0,%1,%2,%3}, [%4];"
                 : "=r"(r0), "=r"(r1), "=r"(r2), "=r"(r3) : "r"(addr));
}
__device__ __forceinline__ void ldsm_x2(uint32_t& r0, uint32_t& r1, uint32_t addr) {
    asm volatile("ldmatrix.sync.aligned.m8n8.x2.shared.b16 {%0,%1}, [%2];"
                 : "=r"(r0), "=r"(r1) : "r"(addr));
}
__device__ __forceinline__ void mma_f16(float* d, const uint32_t* a, const uint32_t* b) {
    asm volatile(
        "mma.sync.aligned.m16n8k16.row.col.f32.f16.f16.f32 "
        "{%0,%1,%2,%3}, {%4,%5,%6,%7}, {%8,%9}, {%0,%1,%2,%3};"
        : "+f"(d[0]), "+f"(d[1]), "+f"(d[2]), "+f"(d[3])
        : "r"(a[0]), "r"(a[1]), "r"(a[2]), "r"(a[3]), "r"(b[0]), "r"(b[1]));
}
__device__ __forceinline__ void red_add_v4(float* p, float4 v) {
    asm volatile("red.relaxed.gpu.global.add.v4.f32 [%0], {%1,%2,%3,%4};"
                 :: "l"(p), "f"(v.x), "f"(v.y), "f"(v.z), "f"(v.w) : "memory");
}

// ================= zero histograms + colsum =================
__global__ void zero_small_kernel() {
    int t = blockIdx.x * blockDim.x + threadIdx.x;
    if (t < 2 * NN) g_cnt[t] = 0;
    if (t < 3 * FF) g_colsum[t] = 0.f;
}

// ================= convert X -> fp16 =================
__global__ __launch_bounds__(256) void convert_x_kernel(const float* __restrict__ X, int n) {
    size_t total4 = (size_t)n * (FF / 4);
    size_t stride = (size_t)gridDim.x * blockDim.x;
    for (size_t i4 = (size_t)blockIdx.x * blockDim.x + threadIdx.x; i4 < total4; i4 += stride) {
        float4 x = reinterpret_cast<const float4*>(X)[i4];
        __half2 h0 = __float22half2_rn(make_float2(x.x, x.y));
        __half2 h1 = __float22half2_rn(make_float2(x.z, x.w));
        size_t i = i4 * 4;
        reinterpret_cast<__half2*>(g_xh + i)[0] = h0;
        reinterpret_cast<__half2*>(g_xh + i)[1] = h1;
    }
}

// ================= transpose + convert W -> fp16 =================
__global__ __launch_bounds__(256) void convert_w_kernel(
    const float* __restrict__ W0, const float* __restrict__ W1, const float* __restrict__ W2)
{
    int z = blockIdx.y;
    const float* W = (z == 0) ? W0 : ((z == 1) ? W1 : W2);
    int t = blockIdx.x * 256 + threadIdx.x;
    int k = t & 255;
    int nn = t >> 8;
    g_wth[(size_t)z * 65536 + nn * 256 + k] = __float2half_rn(W[k * 256 + nn]);
}

// ================= HMMA GEMM (plain fp16): z<2 -> fp16 xw, z==2 -> relu fp32 mlp
static constexpr int TSTRIDE = 40;
static constexpr int TILE_B = 128 * TSTRIDE * 2;
static constexpr int STAGE_B = 2 * TILE_B;          // A, B
static constexpr uint32_t GEMM_SMEM_BYTES = 2 * STAGE_B + 256;

__global__ __launch_bounds__(256, 2) void gemm_mma_kernel(int n)
{
    extern __shared__ char dynsmem[];
    uint32_t raw = smem_u32(dynsmem);
    uint32_t base = (raw + 127) & ~127u;

    const int z = blockIdx.z;
    const __half* __restrict__ WH = g_wth + (size_t)z * 65536;

    const int row0 = blockIdx.x * 128;
    const int col0 = blockIdx.y * 128;
    const int tid = threadIdx.x;
    const int wid = tid >> 5;
    const int lane = tid & 31;
    const int warp_m = wid & 1;
    const int warp_n = wid >> 1;

    const uint32_t AT = 0, BT = TILE_B;

    auto load_chunk = [&](int s, int c) {
        const uint32_t st = base + s * STAGE_B;
        const int k0 = c * 32;
#pragma unroll
        for (int it = 0; it < 2; it++) {
            int idx = tid + it * 256;
            int r = idx >> 2;
            int q = idx & 3;
            uint32_t dsto = (uint32_t)(r * (TSTRIDE * 2) + q * 16);
            int gr = row0 + r;
            uint32_t sz = (gr < n) ? 16u : 0u;
            const __half* sa = g_xh + (size_t)(gr < n ? gr : 0) * FF + k0 + q * 8;
            cp_async16(st + AT + dsto, sa, sz);
            int nr = col0 + r;
            cp_async16(st + BT + dsto, WH + (size_t)nr * FF + k0 + q * 8, 16);
        }
        CP_COMMIT();
    };

    float acc[4][4][4];
#pragma unroll
    for (int i = 0; i < 4; i++)
#pragma unroll
        for (int j = 0; j < 4; j++)
#pragma unroll
            for (int q = 0; q < 4; q++) acc[i][j][q] = 0.f;

    const uint32_t a_off = (uint32_t)((warp_m * 64 + (lane & 15)) * (TSTRIDE * 2) + (lane >> 4) * 16);
    const uint32_t b_off = (uint32_t)((warp_n * 32 + (lane & 7)) * (TSTRIDE * 2) + ((lane >> 3) & 1) * 16);

    load_chunk(0, 0);

    for (int c = 0; c < 8; c++) {
        const int s = c & 1;
        if (c < 7) load_chunk(s ^ 1, c + 1);
        if (c < 7) { CP_WAIT1(); } else { CP_WAIT0(); }
        __syncthreads();

        const uint32_t st = base + s * STAGE_B;
#pragma unroll
        for (int ks = 0; ks < 2; ks++) {
            uint32_t ah[4][4], bt[4][2];
#pragma unroll
            for (int mt = 0; mt < 4; mt++) {
                uint32_t ao = st + a_off + (uint32_t)(mt * 16 * TSTRIDE * 2 + ks * 32);
                ldsm_x4(ah[mt][0], ah[mt][1], ah[mt][2], ah[mt][3], ao + AT);
            }
#pragma unroll
            for (int nt = 0; nt < 4; nt++) {
                uint32_t bo = st + b_off + (uint32_t)(nt * 8 * TSTRIDE * 2 + ks * 32);
                ldsm_x2(bt[nt][0], bt[nt][1], bo + BT);
            }
#pragma unroll
            for (int mt = 0; mt < 4; mt++)
#pragma unroll
                for (int nt = 0; nt < 4; nt++)
                    mma_f16(acc[mt][nt], ah[mt], bt[nt]);
        }
        __syncthreads();
    }

    const int er = lane >> 2;
    const int ec = (lane & 3) * 2;
#pragma unroll
    for (int mt = 0; mt < 4; mt++) {
#pragma unroll
        for (int nt = 0; nt < 4; nt++) {
            int col = col0 + warp_n * 32 + nt * 8 + ec;
            int r1 = row0 + warp_m * 64 + mt * 16 + er;
            int r2 = r1 + 8;
            float2 v1 = make_float2(acc[mt][nt][0], acc[mt][nt][1]);
            float2 v2 = make_float2(acc[mt][nt][2], acc[mt][nt][3]);
            if (z == 2) {
                v1.x = fmaxf(v1.x, 0.f); v1.y = fmaxf(v1.y, 0.f);
                v2.x = fmaxf(v2.x, 0.f); v2.y = fmaxf(v2.y, 0.f);
                if (r1 < n) *reinterpret_cast<float2*>(g_mlp + (size_t)r1 * FF + col) = v1;
                if (r2 < n) *reinterpret_cast<float2*>(g_mlp + (size_t)r2 * FF + col) = v2;
            } else {
                __half* outh = g_xwh + (size_t)z * NN * FF;
                __half2 h1 = __float22half2_rn(v1);
                __half2 h2 = __float22half2_rn(v2);
                if (r1 < n) *reinterpret_cast<__half2*>(outh + (size_t)r1 * FF + col) = h1;
                if (r2 < n) *reinterpret_cast<__half2*>(outh + (size_t)r2 * FF + col) = h2;
            }
        }
    }
}

// ================= counting sort: histogram =================
__global__ __launch_bounds__(256) void hist_kernel(
    const int* __restrict__ rowA, const int* __restrict__ rowB, int E)
{
    const int m = blockIdx.y;
    const int* __restrict__ row = (m == 0) ? rowA : rowB;
    int* cnt = g_cnt + m * NN;
    int stride = gridDim.x * blockDim.x;
    for (int i = blockIdx.x * blockDim.x + threadIdx.x; i < E; i += stride)
        atomicAdd(&cnt[row[i]], 1);
}

// ================= counting sort: exclusive scan (1 block per matrix) ============
__global__ __launch_bounds__(1024) void scan_kernel(int E) {
    const int m = blockIdx.x;
    const int* cnt = g_cnt + m * NN;
    int* ptr = g_ptr + m * (NN + 1);
    int* off = g_off + m * NN;
    __shared__ int wsum[32];
    __shared__ int carry_s;
    int tid = threadIdx.x;
    int lane = tid & 31, wid = tid >> 5;
    if (tid == 0) carry_s = 0;
    __syncthreads();
    for (int basei = 0; basei < NN; basei += 1024) {
        int i = basei + tid;
        int v = (i < NN) ? cnt[i] : 0;
        int x = v;
#pragma unroll
        for (int o = 1; o < 32; o <<= 1) {
            int y = __shfl_up_sync(0xffffffffu, x, o);
            if (lane >= o) x += y;
        }
        if (lane == 31) wsum[wid] = x;
        __syncthreads();
        if (wid == 0) {
            int s = wsum[lane];
#pragma unroll
            for (int o = 1; o < 32; o <<= 1) {
                int y = __shfl_up_sync(0xffffffffu, s, o);
                if (lane >= o) s += y;
            }
            wsum[lane] = s;
        }
        __syncthreads();
        int incl = x + (wid > 0 ? wsum[wid - 1] : 0);
        int excl = incl - v + carry_s;
        if (i < NN) { ptr[i] = excl; off[i] = excl; }
        __syncthreads();
        if (tid == 1023) carry_s += incl;
        __syncthreads();
    }
    if (threadIdx.x == 0) ptr[NN] = E;
}

// ================= counting sort: scatter packed (val,col) =================
__global__ __launch_bounds__(256) void scatter_kernel(
    const int* __restrict__ rowA, const int* __restrict__ colA, const float* __restrict__ valA,
    const int* __restrict__ rowB, const int* __restrict__ colB, const float* __restrict__ valB,
    int E)
{
    const int m = blockIdx.y;
    const int* __restrict__ row = (m == 0) ? rowA : rowB;
    const int* __restrict__ col = (m == 0) ? colA : colB;
    const float* __restrict__ val = (m == 0) ? valA : valB;
    int* off = g_off + m * NN;
    ull* edges = g_edges + (size_t)m * EMAX;
    int stride = gridDim.x * blockDim.x;
    for (int i = blockIdx.x * blockDim.x + threadIdx.x; i < E; i += stride) {
        int r = row[i];
        int pos = atomicAdd(&off[r], 1);
        ull e = ((ull)__float_as_uint(val[i]) << 32) | (uint32_t)col[i];
        edges[pos] = e;
    }
}

// ================= CSR SpMM + fused relu colsum (block-reduced REDs) ============
// 8 warps = 8 rows per block. After gather, relu(rows) reduced across warps in
// padded smem; 64 v4-REDs per block update g_colsum.
__global__ __launch_bounds__(256) void spmm_csr_kernel(int n)
{
    __shared__ float ssum[8][264];   // padded: stride 264 breaks 8-way conflicts
    const int m = blockIdx.y;
    const __half* __restrict__ x = g_xwh + (size_t)m * NN * FF;
    float* __restrict__ acc = (m == 0) ? g_acc0 : g_acc1;
    const ull* __restrict__ edges = g_edges + (size_t)m * EMAX;
    const int* __restrict__ ptr = g_ptr + m * (NN + 1);

    int warp = threadIdx.x >> 5;
    int lane = threadIdx.x & 31;
    int r = blockIdx.x * 8 + warp;
    bool active = (r < n);

    float a[8];
#pragma unroll
    for (int i = 0; i < 8; i++) a[i] = 0.f;

    if (active) {
        int s = ptr[r], e = ptr[r + 1];
        for (int b = s; b < e; b += 32) {
            int cntb = min(32, e - b);
            ull my = (b + lane < e) ? __ldg(edges + b + lane) : 0ull;
            for (int j = 0; j < cntb; j++) {
                ull ed = __shfl_sync(0xffffffffu, my, j);
                int c = (int)(uint32_t)ed;
                float v = __uint_as_float((uint32_t)(ed >> 32));
                uint4 h = __ldg(reinterpret_cast<const uint4*>(x + (size_t)c * FF) + lane);
                float2 f0 = __half22float2(*reinterpret_cast<__half2*>(&h.x));
                float2 f1 = __half22float2(*reinterpret_cast<__half2*>(&h.y));
                float2 f2 = __half22float2(*reinterpret_cast<__half2*>(&h.z));
                float2 f3 = __half22float2(*reinterpret_cast<__half2*>(&h.w));
                a[0] = fmaf(v, f0.x, a[0]); a[1] = fmaf(v, f0.y, a[1]);
                a[2] = fmaf(v, f1.x, a[2]); a[3] = fmaf(v, f1.y, a[3]);
                a[4] = fmaf(v, f2.x, a[4]); a[5] = fmaf(v, f2.y, a[5]);
                a[6] = fmaf(v, f3.x, a[6]); a[7] = fmaf(v, f3.y, a[7]);
            }
        }
        float* dst = acc + (size_t)r * FF + lane * 8;
        *reinterpret_cast<float4*>(dst) = make_float4(a[0], a[1], a[2], a[3]);
        *reinterpret_cast<float4*>(dst + 4) = make_float4(a[4], a[5], a[6], a[7]);
    }

    // stash relu(row) (zeros for inactive rows)
#pragma unroll
    for (int i = 0; i < 8; i++)
        ssum[warp][lane * 8 + i] = active ? fmaxf(a[i], 0.f) : 0.f;
    __syncthreads();

    // 256 threads: thread t sums column t over the 8 warps
    int c = threadIdx.x;
    float s = ssum[0][c] + ssum[1][c] + ssum[2][c] + ssum[3][c]
            + ssum[4][c] + ssum[5][c] + ssum[6][c] + ssum[7][c];
    ssum[0][c] = s;   // no sync needed: each thread wrote/reads only column c
    __syncthreads();
    if (threadIdx.x < 64) {
        int c4 = threadIdx.x;
        float4 v = make_float4(ssum[0][c4 * 4], ssum[0][c4 * 4 + 1],
                               ssum[0][c4 * 4 + 2], ssum[0][c4 * 4 + 3]);
        red_add_v4(&g_colsum[m * FF + c4 * 4], v);
    }
}

// ================= column sums: mlp only =================
__global__ __launch_bounds__(256) void colsum_mlp_kernel(int n) {
    int c4 = threadIdx.x & 63;
    int rl = threadIdx.x >> 6;
    float4 s2 = make_float4(0.f, 0.f, 0.f, 0.f);
    for (int r = blockIdx.x * 4 + rl; r < n; r += gridDim.x * 4) {
        float4 mm = reinterpret_cast<const float4*>(g_mlp)[(size_t)r * (FF / 4) + c4];
        s2.x += mm.x; s2.y += mm.y; s2.z += mm.z; s2.w += mm.w;
    }
    red_add_v4(&g_colsum[2 * FF + c4 * 4], s2);
}

// ================= tiny attention precompute =================
__global__ __launch_bounds__(256) void attn_small_kernel(
    const float* __restrict__ Wk0, const float* __restrict__ Wk1, const float* __restrict__ Wk2,
    const float* __restrict__ avA, const float* __restrict__ avA2, const float* __restrict__ avM,
    int n)
{
    __shared__ float m[3][FF];
    __shared__ float kk[3][64];
    int tid = threadIdx.x;
    float invn = 1.0f / (float)n;
    m[0][tid] = g_colsum[tid] * invn;
    m[1][tid] = g_colsum[FF + tid] * invn;
    m[2][tid] = g_colsum[2 * FF + tid] * invn;
    __syncthreads();
    int j = tid >> 6;
    int h = tid & 63;
    if (j < 3) {
        const float* Wk = (j == 0) ? Wk0 : ((j == 1) ? Wk1 : Wk2);
        float s = 0.f;
#pragma unroll 8
        for (int c = 0; c < FF; c++) s += m[j][c] * Wk[c * 64 + h];
        kk[j][h] = s;
    }
    __syncthreads();
#pragma unroll
    for (int jj = 0; jj < 3; jj++) {
        const float* av = (jj == 0) ? avA : ((jj == 1) ? avA2 : avM);
        float s = 0.f;
#pragma unroll 8
        for (int hh = 0; hh < 64; hh++) s += av[tid * 64 + hh] * kk[jj][hh];
        g_v[jj * FF + tid] = s;
    }
}

// ================= final: gates + weighted combine =================
__global__ __launch_bounds__(256) void final_kernel(
    const float* __restrict__ attvec, float* __restrict__ out, int n)
{
    __shared__ float sv[3 * FF];
    __shared__ float sav[9];
    int tid = threadIdx.x;
    for (int i = tid; i < 3 * FF; i += 256) sv[i] = g_v[i];
    if (tid < 9) sav[tid] = attvec[tid];
    __syncthreads();

    int warp = tid >> 5;
    int lane = tid & 31;
    int node = blockIdx.x * 8 + warp;
    if (node >= n) return;

    size_t base = (size_t)node * FF;
    const float4* pa = reinterpret_cast<const float4*>(g_acc0 + base);
    const float4* pb = reinterpret_cast<const float4*>(g_acc1 + base);
    const float4* pm = reinterpret_cast<const float4*>(g_mlp + base);

    float4 a0 = pa[lane], a1 = pa[lane + 32];
    float4 b0 = pb[lane], b1 = pb[lane + 32];
    float4 m0 = pm[lane], m1 = pm[lane + 32];
    a0.x = fmaxf(a0.x, 0.f); a0.y = fmaxf(a0.y, 0.f); a0.z = fmaxf(a0.z, 0.f); a0.w = fmaxf(a0.w, 0.f);
    a1.x = fmaxf(a1.x, 0.f); a1.y = fmaxf(a1.y, 0.f); a1.z = fmaxf(a1.z, 0.f); a1.w = fmaxf(a1.w, 0.f);
    b0.x = fmaxf(b0.x, 0.f); b0.y = fmaxf(b0.y, 0.f); b0.z = fmaxf(b0.z, 0.f); b0.w = fmaxf(b0.w, 0.f);
    b1.x = fmaxf(b1.x, 0.f); b1.y = fmaxf(b1.y, 0.f); b1.z = fmaxf(b1.z, 0.f); b1.w = fmaxf(b1.w, 0.f);

    const float4* v0p = reinterpret_cast<const float4*>(sv);
    const float4* v1p = reinterpret_cast<const float4*>(sv + FF);
    const float4* v2p = reinterpret_cast<const float4*>(sv + 2 * FF);
    float4 v00 = v0p[lane], v01 = v0p[lane + 32];
    float4 v10 = v1p[lane], v11 = v1p[lane + 32];
    float4 v20 = v2p[lane], v21 = v2p[lane + 32];

    float d0 = a0.x * v00.x + a0.y * v00.y + a0.z * v00.z + a0.w * v00.w
             + a1.x * v01.x + a1.y * v01.y + a1.z * v01.z + a1.w * v01.w;
    float d1 = b0.x * v10.x + b0.y * v10.y + b0.z * v10.z + b0.w * v10.w
             + b1.x * v11.x + b1.y * v11.y + b1.z * v11.z + b1.w * v11.w;
    float d2 = m0.x * v20.x + m0.y * v20.y + m0.z * v20.z + m0.w * v20.w
             + m1.x * v21.x + m1.y * v21.y + m1.z * v21.z + m1.w * v21.w;

#pragma unroll
    for (int o = 16; o > 0; o >>= 1) {
        d0 += __shfl_xor_sync(0xffffffffu, d0, o);
        d1 += __shfl_xor_sync(0xffffffffu, d1, o);
        d2 += __shfl_xor_sync(0xffffffffu, d2, o);
    }

    float s0 = 1.f / (1.f + __expf(-d0));
    float s1 = 1.f / (1.f + __expf(-d1));
    float s2 = 1.f / (1.f + __expf(-d2));
    float zz[3];
#pragma unroll
    for (int i = 0; i < 3; i++)
        zz[i] = (s0 * sav[0 * 3 + i] + s1 * sav[1 * 3 + i] + s2 * sav[2 * 3 + i]) * (1.0f / 3.0f);
    float mx = fmaxf(zz[0], fmaxf(zz[1], zz[2]));
    float e0 = __expf(zz[0] - mx), e1 = __expf(zz[1] - mx), e2 = __expf(zz[2] - mx);
    float inv = 1.f / (e0 + e1 + e2);
    float g0 = 3.f * e0 * inv, g1 = 3.f * e1 * inv, g2 = 3.f * e2 * inv;

    float4 o0, o1;
    o0.x = g0 * a0.x + g1 * b0.x + g2 * m0.x;
    o0.y = g0 * a0.y + g1 * b0.y + g2 * m0.y;
    o0.z = g0 * a0.z + g1 * b0.z + g2 * m0.z;
    o0.w = g0 * a0.w + g1 * b0.w + g2 * m0.w;
    o1.x = g0 * a1.x + g1 * b1.x + g2 * m1.x;
    o1.y = g0 * a1.y + g1 * b1.y + g2 * m1.y;
    o1.z = g0 * a1.z + g1 * b1.z + g2 * m1.z;
    o1.w = g0 * a1.w + g1 * b1.w + g2 * m1.w;

    float4* po = reinterpret_cast<float4*>(out + base);
    po[lane] = o0;
    po[lane + 32] = o1;
}

// ================= launch =================
extern "C" void kernel_launch(void* const* d_in, const int* in_sizes, int n_in,
                              void* d_out, int out_size)
{
    const float* inputx = (const float*)d_in[0];
    const int* row_A = (const int*)d_in[1];
    const int* col_A = (const int*)d_in[2];
    const float* val_A = (const float*)d_in[3];
    const int* row_A2 = (const int*)d_in[4];
    const int* col_A2 = (const int*)d_in[5];
    const float* val_A2 = (const float*)d_in[6];
    const float* weight_A = (const float*)d_in[7];
    const float* weight_A2 = (const float*)d_in[8];
    const float* weight_mlp = (const float*)d_in[9];
    const float* W_k0 = (const float*)d_in[10];
    const float* W_k1 = (const float*)d_in[11];
    const float* W_k2 = (const float*)d_in[12];
    const float* att_vec_A = (const float*)d_in[13];
    const float* att_vec_A2 = (const float*)d_in[14];
    const float* att_vec_mlp = (const float*)d_in[15];
    const float* att_vec = (const float*)d_in[16];
    float* out = (float*)d_out;

    const int n = in_sizes[0] / FF;
    const int E = in_sizes[1];

    // One-time setup on the (non-captured) correctness call.
    static cudaStream_t s2 = nullptr;
    static cudaEvent_t ev_fork = nullptr, ev_join = nullptr;
    static bool configured = false;
    if (!configured) {
        cudaFuncSetAttribute(gemm_mma_kernel, cudaFuncAttributeMaxDynamicSharedMemorySize,
                             GEMM_SMEM_BYTES);
        cudaStreamCreateWithFlags(&s2, cudaStreamNonBlocking);
        cudaEventCreateWithFlags(&ev_fork, cudaEventDisableTiming);
        cudaEventCreateWithFlags(&ev_join, cudaEventDisableTiming);
        configured = true;
    }

    // 0) zero small scratch
    zero_small_kernel<<<(2 * NN + 255) / 256, 256>>>();
    cudaEventRecord(ev_fork, 0);
    cudaStreamWaitEvent(s2, ev_fork, 0);

    // --- stream s2: counting sort of both edge lists by row ---
    {
        dim3 grid(1184, 2);
        hist_kernel<<<grid, 256, 0, s2>>>(row_A, row_A2, E);
        scan_kernel<<<2, 1024, 0, s2>>>(E);
        scatter_kernel<<<grid, 256, 0, s2>>>(row_A, col_A, val_A, row_A2, col_A2, val_A2, E);
    }
    cudaEventRecord(ev_join, s2);

    // --- default stream: converts + GEMM (3 weights, one launch) ---
    convert_x_kernel<<<148 * 20, 256>>>(inputx, n);
    {
        dim3 grid(FF * FF / 256, 3);
        convert_w_kernel<<<grid, 256>>>(weight_A, weight_A2, weight_mlp);
    }
    {
        dim3 grid((n + 127) / 128, FF / 128, 3);
        gemm_mma_kernel<<<grid, 256, GEMM_SMEM_BYTES>>>(n);
    }

    // mlp column sums (only remaining standalone colsum work)
    colsum_mlp_kernel<<<1184, 256>>>(n);

    // join: SpMM needs both GEMM output and sorted edges
    cudaStreamWaitEvent(0, ev_join, 0);

    // 4) CSR SpMM with fused acc colsum (block-reduced REDs)
    {
        dim3 grid((n + 7) / 8, 2);
        spmm_csr_kernel<<<grid, 256>>>(n);
    }

    // 5) gate vectors
    attn_small_kernel<<<1, 256>>>(W_k0, W_k1, W_k2, att_vec_A, att_vec_A2, att_vec_mlp, n);

    // 6) fused gating + combine
    final_kernel<<<(n + 7) / 8, 256>>>(att_vec, out, n);
}